// round 6
// baseline (speedup 1.0000x reference)
#include <cuda_runtime.h>
#include <stdint.h>
#include <math.h>

#define TT    2048
#define HD    1024
#define NH    8
#define SEQ   1024
#define NEXP  8
#define SCALE_F 0.07216878364870322f   // 192^-0.5

// ---------------- scratch ----------------
__device__ float g_wq_hi [1024*1024];
__device__ float g_wq_lo [1024*1024];
__device__ float g_wkv_hi[2048*1024];
__device__ float g_wkv_lo[2048*1024];
__device__ float g_wo_hi [1024*1024];
__device__ float g_wo_lo [1024*1024];
__device__ float g_h_hi  [TT*HD];
__device__ float g_h_lo  [TT*HD];
__device__ float g_o_hi  [TT*1024];
__device__ float g_o_lo  [TT*1024];
__device__ float g_q     [TT*1024];
__device__ float g_kv    [TT*2048];
__device__ float g_x2    [TT*HD];
__device__ float g_h2    [TT*HD];
__device__ float g_gu    [TT*2048];
__device__ float g_act   [TT*1024];
__device__ float g_he    [2*TT*1024];
__device__ float g_ybuf  [2*TT*1024];
__device__ float g_topw  [2*TT];
__device__ float g_pscale[2*TT];
__device__ int   g_topi[2*TT];
__device__ int   g_ptok[2*TT];
__device__ int   g_pdst[2*TT];
__device__ int   g_cnt [NEXP];
__device__ int   g_off [NEXP];

// ---------------- helpers ----------------
__device__ __forceinline__ float cvt_tf32(float x) {
    unsigned u; asm("cvt.rna.tf32.f32 %0, %1;" : "=r"(u) : "f"(x));
    return __uint_as_float(u);
}
__device__ __forceinline__ void mma8(float* d, float a0, float a1, float a2, float a3,
                                     float b0, float b1) {
    unsigned A0=__float_as_uint(a0), A1=__float_as_uint(a1);
    unsigned A2=__float_as_uint(a2), A3=__float_as_uint(a3);
    unsigned B0=__float_as_uint(b0), B1=__float_as_uint(b1);
    asm volatile("mma.sync.aligned.m16n8k8.row.col.f32.tf32.tf32.f32 "
                 "{%0,%1,%2,%3},{%4,%5,%6,%7},{%8,%9},{%0,%1,%2,%3};"
                 : "+f"(d[0]), "+f"(d[1]), "+f"(d[2]), "+f"(d[3])
                 : "r"(A0), "r"(A1), "r"(A2), "r"(A3), "r"(B0), "r"(B1));
}
__device__ __forceinline__ void cp16(uint32_t s, const float* g) {
    asm volatile("cp.async.cg.shared.global [%0], [%1], 16;" :: "r"(s), "l"(g));
}
__device__ __forceinline__ void cpcommit() { asm volatile("cp.async.commit_group;"); }
template<int N> __device__ __forceinline__ void cpwait() {
    asm volatile("cp.async.wait_group %0;" :: "n"(N));
}

// ---------------- pack Wq (nope rows only) + hi/lo split ------------------
__global__ void pack_wq_kernel(const float* __restrict__ Wq,
                               float* __restrict__ hi, float* __restrict__ lo) {
    int r = blockIdx.x;
    int h = r >> 7, d = r & 127;
    float4 v = ((const float4*)(Wq + (size_t)(h*192 + d) * HD))[threadIdx.x];
    float h0=cvt_tf32(v.x), h1=cvt_tf32(v.y), h2=cvt_tf32(v.z), h3=cvt_tf32(v.w);
    ((float4*)(hi + (size_t)r * HD))[threadIdx.x] = make_float4(h0,h1,h2,h3);
    ((float4*)(lo + (size_t)r * HD))[threadIdx.x] =
        make_float4(cvt_tf32(v.x-h0), cvt_tf32(v.y-h1), cvt_tf32(v.z-h2), cvt_tf32(v.w-h3));
}

// ---------------- generic hi/lo split ----------------
__global__ void split_kernel(const float* __restrict__ src,
                             float* __restrict__ hi, float* __restrict__ lo) {
    size_t i = ((size_t)blockIdx.x * 256 + threadIdx.x) * 4;
    float4 v = *(const float4*)(src + i);
    float h0=cvt_tf32(v.x), h1=cvt_tf32(v.y), h2=cvt_tf32(v.z), h3=cvt_tf32(v.w);
    *(float4*)(hi + i) = make_float4(h0,h1,h2,h3);
    *(float4*)(lo + i) =
        make_float4(cvt_tf32(v.x-h0), cvt_tf32(v.y-h1), cvt_tf32(v.z-h2), cvt_tf32(v.w-h3));
}

// ---------------- rmsnorm (SPLIT=1: write hi/lo; 0: fp32) -----------------
template<int SPLIT>
__global__ void rmsnorm_kernel(const float* __restrict__ x, const float* __restrict__ w,
                               float* __restrict__ out, float* __restrict__ out_lo) {
    int t = blockIdx.x;
    const float* xr = x + (size_t)t * HD;
    float ss = 0.f;
    for (int i = threadIdx.x; i < HD; i += 256) { float v = xr[i]; ss += v * v; }
    __shared__ float red[256];
    red[threadIdx.x] = ss; __syncthreads();
    for (int o = 128; o > 0; o >>= 1) {
        if (threadIdx.x < o) red[threadIdx.x] += red[threadIdx.x + o];
        __syncthreads();
    }
    float inv = rsqrtf(red[0] * (1.f / HD) + 1e-6f);
    for (int i = threadIdx.x; i < HD; i += 256) {
        float v = xr[i] * inv * w[i];
        if (SPLIT) {
            float h = cvt_tf32(v);
            out[(size_t)t * HD + i] = h;
            out_lo[(size_t)t * HD + i] = cvt_tf32(v - h);
        } else {
            out[(size_t)t * HD + i] = v;
        }
    }
}

// ---------------- cp.async tensor-core GEMM (NT), multistage --------------
// P=1: single-pass tf32 (raw fp32, HW truncation), 3-stage pipeline
// P=3: 3-pass tf32 from pre-split hi/lo streams, 2-stage pipeline
// MODE: 0 plain, 1 +residual, 2 expert1 (gather+SiLU->g_he), 3 expert2 (scatter)
#define LDR 36
#define MATS (128*LDR)
template<int P, int MODE>
__global__ void __launch_bounds__(256, (P==1)?2:1)
gemm_cp(const float* __restrict__ Ah_, const float* __restrict__ Al_,
        const float* __restrict__ Bh_, const float* __restrict__ Bl_,
        float* __restrict__ C, const float* __restrict__ R,
        int K, int lda, int ldb, int ldc) {
    extern __shared__ float smf[];
    const int SST = ((P==3)?4:2) * MATS;
    const int NSTAGE = (P==1) ? 3 : 2;
    const int bm = blockIdx.y << 7, bn = blockIdx.x << 7;
    int off = 0, cnt = 0x7fffffff;
    const float* Bh = Bh_;
    if (MODE >= 2) {
        int e = blockIdx.z;
        cnt = g_cnt[e];
        if (cnt == 0 || bm >= cnt) return;
        off = g_off[e];
        Bh = Bh_ + (size_t)e * 1024 * 1024;
    }
    __shared__ int rowA[128];
    const int tid = threadIdx.x;
    if (MODE >= 2) {
        if (tid < 128) {
            int gr = bm + tid; if (gr >= cnt) gr = cnt - 1;
            rowA[tid] = (MODE == 2) ? g_ptok[off + gr] : (off + gr);
        }
        __syncthreads();
    }
    const int lane = tid & 31, w = tid >> 5;
    const int g2 = lane >> 2, t4 = lane & 3;
    const int wm = (w >> 2) << 6, wn = (w & 3) << 5;
    const int seg = (tid & 7) << 2, rb = tid >> 3;
    uint32_t sbase = (uint32_t)__cvta_generic_to_shared(smf);

    auto fill = [&](int st, int k0) {
        uint32_t s0 = sbase + (uint32_t)(st * SST) * 4u;
#pragma unroll
        for (int i = 0; i < 4; i++) {
            int row = rb + (i << 5);
            uint32_t so = (uint32_t)(row * LDR + seg) * 4u;
            const float* ga;
            if (MODE >= 2) ga = Ah_ + (size_t)rowA[row] * lda + k0 + seg;
            else           ga = Ah_ + (size_t)(bm + row) * lda + k0 + seg;
            cp16(s0 + so, ga);
            if (P == 3)
                cp16(s0 + (uint32_t)MATS*4u + so, Al_ + (size_t)(bm + row) * lda + k0 + seg);
            cp16(s0 + (uint32_t)((P==3?2:1)*MATS)*4u + so,
                 Bh + (size_t)(bn + row) * ldb + k0 + seg);
            if (P == 3)
                cp16(s0 + (uint32_t)(3*MATS)*4u + so, Bl_ + (size_t)(bn + row) * ldb + k0 + seg);
        }
        cpcommit();
    };

    float acc[4][4][4];
#pragma unroll
    for (int i = 0; i < 4; i++)
#pragma unroll
        for (int j = 0; j < 4; j++)
#pragma unroll
            for (int q = 0; q < 4; q++) acc[i][j][q] = 0.f;

    auto compute = [&](int st) {
        const float* SA  = smf + st * SST;
        const float* SAl = SA + MATS;
        const float* SB  = SA + ((P==3)?2:1) * MATS;
        const float* SBl = SA + 3 * MATS;
#pragma unroll
        for (int kb = 0; kb < 4; kb++) {
            int kc = (kb << 3) + t4;
            float ah[4][4], al[4][4], bh[4][2], bl[4][2];
#pragma unroll
            for (int i = 0; i < 4; i++) {
                int m = (wm + (i << 4) + g2) * LDR;
                ah[i][0] = SA[m + kc];            ah[i][1] = SA[m + (LDR<<3) + kc];
                ah[i][2] = SA[m + kc + 4];        ah[i][3] = SA[m + (LDR<<3) + kc + 4];
                if (P == 3) {
                    al[i][0] = SAl[m + kc];       al[i][1] = SAl[m + (LDR<<3) + kc];
                    al[i][2] = SAl[m + kc + 4];   al[i][3] = SAl[m + (LDR<<3) + kc + 4];
                }
            }
#pragma unroll
            for (int j = 0; j < 4; j++) {
                int n = (wn + (j << 3) + g2) * LDR;
                bh[j][0] = SB[n + kc];  bh[j][1] = SB[n + kc + 4];
                if (P == 3) { bl[j][0] = SBl[n + kc]; bl[j][1] = SBl[n + kc + 4]; }
            }
#pragma unroll
            for (int i = 0; i < 4; i++)
#pragma unroll
                for (int j = 0; j < 4; j++) {
                    mma8(acc[i][j], ah[i][0],ah[i][1],ah[i][2],ah[i][3], bh[j][0],bh[j][1]);
                    if (P == 3) {
                        mma8(acc[i][j], ah[i][0],ah[i][1],ah[i][2],ah[i][3], bl[j][0],bl[j][1]);
                        mma8(acc[i][j], al[i][0],al[i][1],al[i][2],al[i][3], bh[j][0],bh[j][1]);
                    }
                }
        }
    };

    const int NS = K >> 5;
    // prologue: fill stages 0..NSTAGE-2
    fill(0, 0);
    if (NSTAGE == 3 && NS > 1) fill(1, 32);
    for (int ks = 0; ks < NS; ks++) {
        if (NSTAGE == 3) cpwait<1>(); else cpwait<0>();
        __syncthreads();                 // one barrier per iteration
        int nf = ks + NSTAGE - 1;
        if (nf < NS) fill(nf % NSTAGE, nf << 5);
        compute(ks % NSTAGE);
    }

    // epilogue
#pragma unroll
    for (int i = 0; i < 4; i++) {
#pragma unroll
        for (int j = 0; j < 4; j++) {
            int m0 = bm + wm + 16*i + g2, m1 = m0 + 8;
            int nc = bn + wn + 8*j + 2*t4;
            float2 v0 = make_float2(acc[i][j][0], acc[i][j][1]);
            float2 v1 = make_float2(acc[i][j][2], acc[i][j][3]);
            if (MODE == 0 || MODE == 1) {
                size_t o0 = (size_t)m0 * ldc + nc, o1 = (size_t)m1 * ldc + nc;
                if (MODE == 1) {
                    float2 r0 = *(const float2*)(R + o0);
                    float2 r1 = *(const float2*)(R + o1);
                    v0.x += r0.x; v0.y += r0.y; v1.x += r1.x; v1.y += r1.y;
                }
                *(float2*)(C + o0) = v0;
                *(float2*)(C + o1) = v1;
            } else if (MODE == 2) {
                if (m0 < cnt) {
                    float2 s = make_float2(v0.x/(1.f+expf(-v0.x)), v0.y/(1.f+expf(-v0.y)));
                    *(float2*)(g_he + (size_t)(off+m0)*1024 + nc) = s;
                }
                if (m1 < cnt) {
                    float2 s = make_float2(v1.x/(1.f+expf(-v1.x)), v1.y/(1.f+expf(-v1.y)));
                    *(float2*)(g_he + (size_t)(off+m1)*1024 + nc) = s;
                }
            } else {
                if (m0 < cnt) {
                    int p = off + m0; float sc = g_pscale[p]; int d = g_pdst[p];
                    *(float2*)(g_ybuf + (size_t)d*1024 + nc) = make_float2(v0.x*sc, v0.y*sc);
                }
                if (m1 < cnt) {
                    int p = off + m1; float sc = g_pscale[p]; int d = g_pdst[p];
                    *(float2*)(g_ybuf + (size_t)d*1024 + nc) = make_float2(v1.x*sc, v1.y*sc);
                }
            }
        }
    }
}

// ---------------- flash attention: tensor-core tf32 ----------------------
#define A_LDQ 132
#define A_LDV 136
#define A_LDP 68
#define ATTN2_FLOATS (4*64*A_LDQ + 64*A_LDV + 64*A_LDP + 128 + 128 + 64 + 64)
__global__ void __launch_bounds__(256, 1) attn_tc_kernel(const float* __restrict__ q,
                                                         const float* __restrict__ kv,
                                                         float* __restrict__ ohi,
                                                         float* __restrict__ olo) {
    extern __shared__ float sm[];
    float* Qh   = sm;
    float* Ql   = Qh + 64*A_LDQ;
    float* Kh   = Ql + 64*A_LDQ;
    float* Kl   = Kh + 64*A_LDQ;
    float* Vt   = Kl + 64*A_LDQ;
    float* Ps   = Vt + 64*A_LDV;
    float* red  = Ps + 64*A_LDP;
    float* red2 = red + 128;
    float* mrow = red2 + 128;
    float* lrow = mrow + 64;

    const int qt = 15 - blockIdx.x;
    const int head = blockIdx.y, b = blockIdx.z;
    const int tid = threadIdx.x, lane = tid & 31, wid = tid >> 5;
    const int g2 = lane >> 2, t4 = lane & 3;
    const int wm = (wid & 3) << 4;
    const int wn = wid >> 2;
    const int qbase = qt << 6;
    const size_t tok0 = (size_t)b * SEQ;
    const int hoff = head << 7;

#pragma unroll
    for (int it = 0; it < 8; it++) {
        int lin = tid + (it << 8);
        int r = lin >> 5, c4 = (lin & 31) << 2;
        float4 v = *(const float4*)(q + (tok0 + qbase + r) * 1024 + hoff + c4);
        float h0 = cvt_tf32(v.x), h1 = cvt_tf32(v.y), h2 = cvt_tf32(v.z), h3 = cvt_tf32(v.w);
        *(float4*)(Qh + r*A_LDQ + c4) = make_float4(h0, h1, h2, h3);
        *(float4*)(Ql + r*A_LDQ + c4) =
            make_float4(cvt_tf32(v.x-h0), cvt_tf32(v.y-h1), cvt_tf32(v.z-h2), cvt_tf32(v.w-h3));
    }
    if (tid < 64) { mrow[tid] = -1e30f; lrow[tid] = 0.f; }

    float oacc[8][4];
#pragma unroll
    for (int j = 0; j < 8; j++)
#pragma unroll
        for (int c = 0; c < 4; c++) oacc[j][c] = 0.f;

    const int r0 = wm + g2, r1 = r0 + 8;

    for (int kt = 0; kt <= qt; kt++) {
        __syncthreads();
#pragma unroll
        for (int it = 0; it < 8; it++) {
            int lin = tid + (it << 8);
            int r = lin >> 5, c4 = (lin & 31) << 2;
            const float* krow = kv + (tok0 + (kt<<6) + r) * 2048 + hoff;
            float4 kvv = *(const float4*)(krow + c4);
            float4 vv  = *(const float4*)(krow + 1024 + c4);
            float h0 = cvt_tf32(kvv.x), h1 = cvt_tf32(kvv.y);
            float h2 = cvt_tf32(kvv.z), h3 = cvt_tf32(kvv.w);
            *(float4*)(Kh + r*A_LDQ + c4) = make_float4(h0, h1, h2, h3);
            *(float4*)(Kl + r*A_LDQ + c4) =
                make_float4(cvt_tf32(kvv.x-h0), cvt_tf32(kvv.y-h1),
                            cvt_tf32(kvv.z-h2), cvt_tf32(kvv.w-h3));
            *(float4*)(Vt + r*A_LDV + c4) =
                make_float4(cvt_tf32(vv.x), cvt_tf32(vv.y), cvt_tf32(vv.z), cvt_tf32(vv.w));
        }
        __syncthreads();
        float sacc[4][4];
#pragma unroll
        for (int j = 0; j < 4; j++)
#pragma unroll
            for (int c = 0; c < 4; c++) sacc[j][c] = 0.f;
#pragma unroll
        for (int kk = 0; kk < 16; kk++) {
            int kc = (kk << 3) + t4;
            int ar0 = r0 * A_LDQ, ar1 = r1 * A_LDQ;
            float ah0 = Qh[ar0+kc], ah1 = Qh[ar1+kc], ah2 = Qh[ar0+kc+4], ah3 = Qh[ar1+kc+4];
            float al0 = Ql[ar0+kc], al1 = Ql[ar1+kc], al2 = Ql[ar0+kc+4], al3 = Ql[ar1+kc+4];
#pragma unroll
            for (int j = 0; j < 4; j++) {
                int br = ((wn<<5) + (j<<3) + g2) * A_LDQ;
                float bh0 = Kh[br+kc], bh1 = Kh[br+kc+4];
                float bl0 = Kl[br+kc], bl1 = Kl[br+kc+4];
                mma8(sacc[j], ah0, ah1, ah2, ah3, bh0, bh1);
                mma8(sacc[j], ah0, ah1, ah2, ah3, bl0, bl1);
                mma8(sacc[j], al0, al1, al2, al3, bh0, bh1);
            }
        }
#pragma unroll
        for (int j = 0; j < 4; j++)
#pragma unroll
            for (int c = 0; c < 4; c++) sacc[j][c] *= SCALE_F;
        if (kt == qt) {
            int grow0 = qbase + r0, grow1 = qbase + r1;
#pragma unroll
            for (int j = 0; j < 4; j++) {
                int col = (kt<<6) + (wn<<5) + (j<<3) + (t4<<1);
                if (col   > grow0) sacc[j][0] = -1e30f;
                if (col+1 > grow0) sacc[j][1] = -1e30f;
                if (col   > grow1) sacc[j][2] = -1e30f;
                if (col+1 > grow1) sacc[j][3] = -1e30f;
            }
        }
        float mx0 = fmaxf(fmaxf(sacc[0][0], sacc[0][1]), fmaxf(sacc[1][0], sacc[1][1]));
        mx0 = fmaxf(mx0, fmaxf(fmaxf(sacc[2][0], sacc[2][1]), fmaxf(sacc[3][0], sacc[3][1])));
        float mx1 = fmaxf(fmaxf(sacc[0][2], sacc[0][3]), fmaxf(sacc[1][2], sacc[1][3]));
        mx1 = fmaxf(mx1, fmaxf(fmaxf(sacc[2][2], sacc[2][3]), fmaxf(sacc[3][2], sacc[3][3])));
        mx0 = fmaxf(mx0, __shfl_xor_sync(0xffffffffu, mx0, 1));
        mx0 = fmaxf(mx0, __shfl_xor_sync(0xffffffffu, mx0, 2));
        mx1 = fmaxf(mx1, __shfl_xor_sync(0xffffffffu, mx1, 1));
        mx1 = fmaxf(mx1, __shfl_xor_sync(0xffffffffu, mx1, 2));
        if (t4 == 0) { red[(r0<<1) + wn] = mx0; red[(r1<<1) + wn] = mx1; }
        __syncthreads();
        float mo0 = mrow[r0], mo1 = mrow[r1];
        float mn0 = fmaxf(mo0, fmaxf(red[r0<<1], red[(r0<<1)+1]));
        float mn1 = fmaxf(mo1, fmaxf(red[r1<<1], red[(r1<<1)+1]));
        float f0 = __expf(mo0 - mn0), f1 = __expf(mo1 - mn1);
        float ps0 = 0.f, ps1 = 0.f;
#pragma unroll
        for (int j = 0; j < 4; j++) {
            float p0 = __expf(sacc[j][0] - mn0), p1 = __expf(sacc[j][1] - mn0);
            float p2 = __expf(sacc[j][2] - mn1), p3 = __expf(sacc[j][3] - mn1);
            ps0 += p0 + p1; ps1 += p2 + p3;
            int pc = (wn<<5) + (j<<3) + (t4<<1);
            *(float2*)(Ps + r0*A_LDP + pc) = make_float2(cvt_tf32(p0), cvt_tf32(p1));
            *(float2*)(Ps + r1*A_LDP + pc) = make_float2(cvt_tf32(p2), cvt_tf32(p3));
        }
        ps0 += __shfl_xor_sync(0xffffffffu, ps0, 1);
        ps0 += __shfl_xor_sync(0xffffffffu, ps0, 2);
        ps1 += __shfl_xor_sync(0xffffffffu, ps1, 1);
        ps1 += __shfl_xor_sync(0xffffffffu, ps1, 2);
        if (t4 == 0) { red2[(r0<<1) + wn] = ps0; red2[(r1<<1) + wn] = ps1; }
#pragma unroll
        for (int j = 0; j < 8; j++) {
            oacc[j][0] *= f0; oacc[j][1] *= f0;
            oacc[j][2] *= f1; oacc[j][3] *= f1;
        }
        __syncthreads();
        if (wn == 0 && t4 == 0) {
            mrow[r0] = mn0; lrow[r0] = lrow[r0] * f0 + red2[r0<<1] + red2[(r0<<1)+1];
            mrow[r1] = mn1; lrow[r1] = lrow[r1] * f1 + red2[r1<<1] + red2[(r1<<1)+1];
        }
#pragma unroll
        for (int kk = 0; kk < 8; kk++) {
            int kc = (kk << 3) + t4;
            float a0 = Ps[r0*A_LDP + kc], a1 = Ps[r1*A_LDP + kc];
            float a2 = Ps[r0*A_LDP + kc + 4], a3 = Ps[r1*A_LDP + kc + 4];
#pragma unroll
            for (int j = 0; j < 8; j++) {
                int bc = (wn<<6) + (j<<3) + g2;
                float b0 = Vt[kc*A_LDV + bc];
                float b1 = Vt[(kc+4)*A_LDV + bc];
                mma8(oacc[j], a0, a1, a2, a3, b0, b1);
            }
        }
    }
    __syncthreads();
    float il0 = 1.f / lrow[r0], il1 = 1.f / lrow[r1];
#pragma unroll
    for (int j = 0; j < 8; j++) {
        int col = hoff + (wn<<6) + (j<<3) + (t4<<1);
        size_t o0 = (tok0 + qbase + r0) * 1024 + col;
        size_t o1 = (tok0 + qbase + r1) * 1024 + col;
        float v00 = oacc[j][0]*il0, v01 = oacc[j][1]*il0;
        float v10 = oacc[j][2]*il1, v11 = oacc[j][3]*il1;
        float h00 = cvt_tf32(v00), h01 = cvt_tf32(v01);
        float h10 = cvt_tf32(v10), h11 = cvt_tf32(v11);
        *(float2*)(ohi + o0) = make_float2(h00, h01);
        *(float2*)(ohi + o1) = make_float2(h10, h11);
        *(float2*)(olo + o0) = make_float2(cvt_tf32(v00-h00), cvt_tf32(v01-h01));
        *(float2*)(olo + o1) = make_float2(cvt_tf32(v10-h10), cvt_tf32(v11-h11));
    }
}

// ---------------- MoE gate ---------------
__global__ void gate_kernel(const float* __restrict__ h2, const float* __restrict__ gw) {
    int t = blockIdx.x;
    int w = threadIdx.x >> 5, lane = threadIdx.x & 31;
    const float* xr = h2 + (size_t)t * HD;
    const float* gr = gw + (size_t)w * HD;
    float ss = 0.f;
    for (int i = lane; i < HD; i += 32) ss += xr[i] * gr[i];
#pragma unroll
    for (int o = 16; o > 0; o >>= 1) ss += __shfl_down_sync(0xffffffffu, ss, o);
    __shared__ float lg[NEXP];
    if (lane == 0) lg[w] = ss;
    __syncthreads();
    if (threadIdx.x == 0) {
        int i1 = 0;
#pragma unroll
        for (int e = 1; e < NEXP; e++) if (lg[e] > lg[i1]) i1 = e;
        int i2 = (i1 == 0) ? 1 : 0;
#pragma unroll
        for (int e = 0; e < NEXP; e++) if (e != i1 && lg[e] > lg[i2]) i2 = e;
        float e2 = expf(lg[i2] - lg[i1]);
        float inv = 1.f / (1.f + e2);
        g_topi[2*t]   = i1; g_topw[2*t]   = inv;
        g_topi[2*t+1] = i2; g_topw[2*t+1] = e2 * inv;
    }
}

// ---------------- deterministic expert grouping --------------------------
__global__ void route_group_kernel() {
    __shared__ int hist[NEXP * 256];
    __shared__ int soff[NEXP + 1];
    __shared__ int stot[NEXP];
    int tid = threadIdx.x;
    int t0 = tid * 8;
    int lc[NEXP];
#pragma unroll
    for (int e = 0; e < NEXP; e++) lc[e] = 0;
    for (int t = t0; t < t0 + 8; t++) {
        lc[g_topi[2*t]]++; lc[g_topi[2*t+1]]++;
    }
#pragma unroll
    for (int e = 0; e < NEXP; e++) hist[e * 256 + tid] = lc[e];
    __syncthreads();
    if (tid < NEXP) {
        int a = 0;
        for (int i = 0; i < 256; i++) { int v = hist[tid*256+i]; hist[tid*256+i] = a; a += v; }
        stot[tid] = a;
    }
    __syncthreads();
    if (tid == 0) {
        int a = 0;
        for (int e = 0; e < NEXP; e++) { soff[e] = a; g_off[e] = a; g_cnt[e] = stot[e]; a += stot[e]; }
        soff[NEXP] = a;
    }
    __syncthreads();
    int pos[NEXP];
#pragma unroll
    for (int e = 0; e < NEXP; e++) pos[e] = soff[e] + hist[e * 256 + tid];
    for (int t = t0; t < t0 + 8; t++) {
        for (int s2 = 0; s2 < 2; s2++) {
            int e = g_topi[2*t + s2];
            int p = pos[e]++;
            g_ptok[p] = t; g_pdst[p] = 2*t + s2; g_pscale[p] = g_topw[2*t + s2];
        }
    }
}

// ---------------- elementwise tails --------------------------------------
__global__ void swiglu_kernel(const float* __restrict__ gu, float* __restrict__ act) {
    int t = blockIdx.x, i = threadIdx.x;
    float4 g = *(const float4*)(gu + (size_t)t*2048 + 4*i);
    float4 u = *(const float4*)(gu + (size_t)t*2048 + 1024 + 4*i);
    float4 r;
    r.x = g.x / (1.f + expf(-g.x)) * u.x;
    r.y = g.y / (1.f + expf(-g.y)) * u.y;
    r.z = g.z / (1.f + expf(-g.z)) * u.z;
    r.w = g.w / (1.f + expf(-g.w)) * u.w;
    *(float4*)(act + (size_t)t*HD + 4*i) = r;
}

__global__ void add_routed_kernel(float* __restrict__ out) {
    int t = blockIdx.x, i = threadIdx.x;
    float4 a = *(const float4*)(out + (size_t)t*HD + 4*i);
    float4 y0 = *(const float4*)(g_ybuf + (size_t)(2*t)*HD + 4*i);
    float4 y1 = *(const float4*)(g_ybuf + (size_t)(2*t+1)*HD + 4*i);
    a.x += y0.x + y1.x; a.y += y0.y + y1.y; a.z += y0.z + y1.z; a.w += y0.w + y1.w;
    *(float4*)(out + (size_t)t*HD + 4*i) = a;
}

// ---------------- launch ---------------------------------------------------
extern "C" void kernel_launch(void* const* d_in, const int* in_sizes, int n_in,
                              void* d_out, int out_size) {
    const float* x    = (const float*)d_in[0];
    const float* ln1  = (const float*)d_in[2];
    const float* ln2  = (const float*)d_in[3];
    const float* Wq   = (const float*)d_in[4];
    const float* Wkv  = (const float*)d_in[5];
    const float* Wo   = (const float*)d_in[6];
    const float* gate = (const float*)d_in[7];
    const float* w1   = (const float*)d_in[8];
    const float* w2   = (const float*)d_in[9];
    const float* sgu  = (const float*)d_in[10];
    const float* sdwn = (const float*)d_in[11];
    float* out = (float*)d_out;

    float *p_wq_hi,*p_wq_lo,*p_wkv_hi,*p_wkv_lo,*p_wo_hi,*p_wo_lo;
    float *p_h_hi,*p_h_lo,*p_o_hi,*p_o_lo;
    float *p_q,*p_kv,*p_x2,*p_h2,*p_gu,*p_act,*p_he;
    cudaGetSymbolAddress((void**)&p_wq_hi,  g_wq_hi);
    cudaGetSymbolAddress((void**)&p_wq_lo,  g_wq_lo);
    cudaGetSymbolAddress((void**)&p_wkv_hi, g_wkv_hi);
    cudaGetSymbolAddress((void**)&p_wkv_lo, g_wkv_lo);
    cudaGetSymbolAddress((void**)&p_wo_hi,  g_wo_hi);
    cudaGetSymbolAddress((void**)&p_wo_lo,  g_wo_lo);
    cudaGetSymbolAddress((void**)&p_h_hi,   g_h_hi);
    cudaGetSymbolAddress((void**)&p_h_lo,   g_h_lo);
    cudaGetSymbolAddress((void**)&p_o_hi,   g_o_hi);
    cudaGetSymbolAddress((void**)&p_o_lo,   g_o_lo);
    cudaGetSymbolAddress((void**)&p_q,      g_q);
    cudaGetSymbolAddress((void**)&p_kv,     g_kv);
    cudaGetSymbolAddress((void**)&p_x2,     g_x2);
    cudaGetSymbolAddress((void**)&p_h2,     g_h2);
    cudaGetSymbolAddress((void**)&p_gu,     g_gu);
    cudaGetSymbolAddress((void**)&p_act,    g_act);
    cudaGetSymbolAddress((void**)&p_he,     g_he);

    const int ATTN2_SMEM = ATTN2_FLOATS * 4;
    cudaFuncSetAttribute(attn_tc_kernel, cudaFuncAttributeMaxDynamicSharedMemorySize, ATTN2_SMEM);
    const int SM_P1 = 3 * 2 * MATS * 4;   // 110592 B (3-stage)
    const int SM_P3 = 2 * 4 * MATS * 4;   // 147456 B (2-stage)
    cudaFuncSetAttribute(gemm_cp<3,0>, cudaFuncAttributeMaxDynamicSharedMemorySize, SM_P3);
    cudaFuncSetAttribute(gemm_cp<3,1>, cudaFuncAttributeMaxDynamicSharedMemorySize, SM_P3);
    cudaFuncSetAttribute(gemm_cp<1,0>, cudaFuncAttributeMaxDynamicSharedMemorySize, SM_P1);
    cudaFuncSetAttribute(gemm_cp<1,1>, cudaFuncAttributeMaxDynamicSharedMemorySize, SM_P1);
    cudaFuncSetAttribute(gemm_cp<1,2>, cudaFuncAttributeMaxDynamicSharedMemorySize, SM_P1);
    cudaFuncSetAttribute(gemm_cp<1,3>, cudaFuncAttributeMaxDynamicSharedMemorySize, SM_P1);

    // weight splits (hi/lo) for routing-critical GEMMs
    pack_wq_kernel<<<1024, 256>>>(Wq, p_wq_hi, p_wq_lo);
    split_kernel<<<2048, 256>>>(Wkv, p_wkv_hi, p_wkv_lo);
    split_kernel<<<1024, 256>>>(Wo, p_wo_hi, p_wo_lo);

    // attention block (tf32 3-pass on routing-critical path)
    rmsnorm_kernel<1><<<TT, 256>>>(x, ln1, p_h_hi, p_h_lo);
    gemm_cp<3,0><<<dim3(8, 16), 256, SM_P3>>>(p_h_hi, p_h_lo, p_wq_hi, p_wq_lo,
                                              p_q, nullptr, 1024, 1024, 1024, 1024);
    gemm_cp<3,0><<<dim3(16,16), 256, SM_P3>>>(p_h_hi, p_h_lo, p_wkv_hi, p_wkv_lo,
                                              p_kv, nullptr, 1024, 1024, 1024, 2048);
    attn_tc_kernel<<<dim3(16, NH, 2), 256, ATTN2_SMEM>>>(p_q, p_kv, p_o_hi, p_o_lo);
    gemm_cp<3,1><<<dim3(8, 16), 256, SM_P3>>>(p_o_hi, p_o_lo, p_wo_hi, p_wo_lo,
                                              p_x2, x, 1024, 1024, 1024, 1024);

    // MoE block
    rmsnorm_kernel<0><<<TT, 256>>>(p_x2, ln2, p_h2, nullptr);
    gate_kernel<<<TT, 256>>>(p_h2, gate);
    route_group_kernel<<<1, 256>>>();
    gemm_cp<1,2><<<dim3(8, 32, NEXP), 256, SM_P1>>>(p_h2, nullptr, w1, nullptr,
                                                    nullptr, nullptr, 1024, 1024, 1024, 1024);
    gemm_cp<1,3><<<dim3(8, 32, NEXP), 256, SM_P1>>>(p_he, nullptr, w2, nullptr,
                                                    nullptr, nullptr, 1024, 1024, 1024, 1024);

    // shared expert
    gemm_cp<1,0><<<dim3(16,16), 256, SM_P1>>>(p_h2, nullptr, sgu, nullptr,
                                              p_gu, nullptr, 1024, 1024, 1024, 2048);
    swiglu_kernel<<<TT, 256>>>(p_gu, p_act);
    gemm_cp<1,1><<<dim3(8, 16), 256, SM_P1>>>(p_act, nullptr, sdwn, nullptr,
                                              out, p_x2, 1024, 1024, 1024, 1024);

    // combine routed experts
    add_routed_kernel<<<TT, 256>>>(out);
}

// round 9
// speedup vs baseline: 1.2107x; 1.2107x over previous
#include <cuda_runtime.h>
#include <cuda_bf16.h>
#include <stdint.h>
#include <math.h>

#define TT    2048
#define HD    1024
#define NH    8
#define SEQ   1024
#define NEXP  8
#define SCALE_F 0.07216878364870322f   // 192^-0.5

typedef __nv_bfloat16 bf16;

// ---------------- scratch ----------------
__device__ bf16  g_wq_hi [1024*1024];
__device__ bf16  g_wq_lo [1024*1024];
__device__ bf16  g_wkv_hi[2048*1024];
__device__ bf16  g_wkv_lo[2048*1024];
__device__ bf16  g_wo_hi [1024*1024];
__device__ bf16  g_wo_lo [1024*1024];
__device__ bf16  g_h_hi  [TT*HD];
__device__ bf16  g_h_lo  [TT*HD];
__device__ bf16  g_o_hi  [TT*1024];
__device__ bf16  g_o_lo  [TT*1024];
__device__ float g_q     [TT*1024];
__device__ float g_kv    [TT*2048];
__device__ float g_x2    [TT*HD];
__device__ float g_h2    [TT*HD];
__device__ float g_gu    [TT*2048];
__device__ float g_act   [TT*1024];
__device__ float g_he    [2*TT*1024];
__device__ float g_ybuf  [2*TT*1024];
__device__ float g_topw  [2*TT];
__device__ float g_pscale[2*TT];
__device__ int   g_topi[2*TT];
__device__ int   g_ptok[2*TT];
__device__ int   g_pdst[2*TT];
__device__ int   g_cnt [NEXP];
__device__ int   g_off [NEXP];

// ---------------- helpers ----------------
__device__ __forceinline__ float cvt_tf32(float x) {
    unsigned u; asm("cvt.rna.tf32.f32 %0, %1;" : "=r"(u) : "f"(x));
    return __uint_as_float(u);
}
__device__ __forceinline__ void mma8(float* d, float a0, float a1, float a2, float a3,
                                     float b0, float b1) {
    unsigned A0=__float_as_uint(a0), A1=__float_as_uint(a1);
    unsigned A2=__float_as_uint(a2), A3=__float_as_uint(a3);
    unsigned B0=__float_as_uint(b0), B1=__float_as_uint(b1);
    asm volatile("mma.sync.aligned.m16n8k8.row.col.f32.tf32.tf32.f32 "
                 "{%0,%1,%2,%3},{%4,%5,%6,%7},{%8,%9},{%0,%1,%2,%3};"
                 : "+f"(d[0]), "+f"(d[1]), "+f"(d[2]), "+f"(d[3])
                 : "r"(A0), "r"(A1), "r"(A2), "r"(A3), "r"(B0), "r"(B1));
}
__device__ __forceinline__ void mma16(float* d, const uint32_t* a, const uint32_t* b) {
    asm volatile("mma.sync.aligned.m16n8k16.row.col.f32.bf16.bf16.f32 "
                 "{%0,%1,%2,%3},{%4,%5,%6,%7},{%8,%9},{%0,%1,%2,%3};"
                 : "+f"(d[0]), "+f"(d[1]), "+f"(d[2]), "+f"(d[3])
                 : "r"(a[0]), "r"(a[1]), "r"(a[2]), "r"(a[3]), "r"(b[0]), "r"(b[1]));
}
__device__ __forceinline__ void ldsm4(uint32_t* r, uint32_t a) {
    asm volatile("ldmatrix.sync.aligned.m8n8.x4.shared.b16 {%0,%1,%2,%3}, [%4];"
                 : "=r"(r[0]), "=r"(r[1]), "=r"(r[2]), "=r"(r[3]) : "r"(a));
}
__device__ __forceinline__ void cp16(uint32_t s, const void* g) {
    asm volatile("cp.async.cg.shared.global [%0], [%1], 16;" :: "r"(s), "l"(g));
}
__device__ __forceinline__ void cpcommit() { asm volatile("cp.async.commit_group;"); }
template<int N> __device__ __forceinline__ void cpwait() {
    asm volatile("cp.async.wait_group %0;" :: "n"(N));
}
__device__ __forceinline__ uint32_t packbf2(float a, float b) {
    __nv_bfloat162 t = __floats2bfloat162_rn(a, b);
    return *(uint32_t*)&t;
}

// ---------------- pack Wq (nope rows only) + bf16 hi/lo split -------------
__global__ void pack_wq_kernel(const float* __restrict__ Wq,
                               bf16* __restrict__ hi, bf16* __restrict__ lo) {
    int r = blockIdx.x;
    int h = r >> 7, d = r & 127;
    float4 v = ((const float4*)(Wq + (size_t)(h*192 + d) * HD))[threadIdx.x];
    float h0 = __bfloat162float(__float2bfloat16_rn(v.x));
    float h1 = __bfloat162float(__float2bfloat16_rn(v.y));
    float h2 = __bfloat162float(__float2bfloat16_rn(v.z));
    float h3 = __bfloat162float(__float2bfloat16_rn(v.w));
    uint2 ph = make_uint2(packbf2(h0, h1), packbf2(h2, h3));
    uint2 pl = make_uint2(packbf2(v.x-h0, v.y-h1), packbf2(v.z-h2, v.w-h3));
    ((uint2*)(hi + (size_t)r * HD))[threadIdx.x] = ph;
    ((uint2*)(lo + (size_t)r * HD))[threadIdx.x] = pl;
}

// ---------------- generic bf16 hi/lo split --------------------------------
__global__ void split_kernel(const float* __restrict__ src,
                             bf16* __restrict__ hi, bf16* __restrict__ lo) {
    size_t i = ((size_t)blockIdx.x * 256 + threadIdx.x);
    float4 v = ((const float4*)src)[i];
    float h0 = __bfloat162float(__float2bfloat16_rn(v.x));
    float h1 = __bfloat162float(__float2bfloat16_rn(v.y));
    float h2 = __bfloat162float(__float2bfloat16_rn(v.z));
    float h3 = __bfloat162float(__float2bfloat16_rn(v.w));
    ((uint2*)hi)[i] = make_uint2(packbf2(h0, h1), packbf2(h2, h3));
    ((uint2*)lo)[i] = make_uint2(packbf2(v.x-h0, v.y-h1), packbf2(v.z-h2, v.w-h3));
}

// ---------------- rmsnorm (SPLIT=1: bf16 hi/lo; 0: fp32) ------------------
template<int SPLIT>
__global__ void rmsnorm_kernel(const float* __restrict__ x, const float* __restrict__ w,
                               void* __restrict__ out, bf16* __restrict__ out_lo) {
    int t = blockIdx.x;
    float4 v = ((const float4*)(x + (size_t)t * HD))[threadIdx.x];
    float ss = v.x*v.x + v.y*v.y + v.z*v.z + v.w*v.w;
    __shared__ float red[256];
    red[threadIdx.x] = ss; __syncthreads();
    for (int o = 128; o > 0; o >>= 1) {
        if (threadIdx.x < o) red[threadIdx.x] += red[threadIdx.x + o];
        __syncthreads();
    }
    float inv = rsqrtf(red[0] * (1.f / HD) + 1e-6f);
    float4 wv = ((const float4*)w)[threadIdx.x];
    float o0 = v.x*inv*wv.x, o1 = v.y*inv*wv.y, o2 = v.z*inv*wv.z, o3 = v.w*inv*wv.w;
    if (SPLIT) {
        float h0 = __bfloat162float(__float2bfloat16_rn(o0));
        float h1 = __bfloat162float(__float2bfloat16_rn(o1));
        float h2 = __bfloat162float(__float2bfloat16_rn(o2));
        float h3 = __bfloat162float(__float2bfloat16_rn(o3));
        ((uint2*)((bf16*)out + (size_t)t * HD))[threadIdx.x] =
            make_uint2(packbf2(h0, h1), packbf2(h2, h3));
        ((uint2*)(out_lo + (size_t)t * HD))[threadIdx.x] =
            make_uint2(packbf2(o0-h0, o1-h1), packbf2(o2-h2, o3-h3));
    } else {
        ((float4*)((float*)out + (size_t)t * HD))[threadIdx.x] = make_float4(o0, o1, o2, o3);
    }
}

// ---------------- bf16 4-pass GEMM (NT), ldmatrix + cp.async --------------
// C = Ahi*Bhi + Ahi*Blo + Alo*Bhi + Alo*Blo  (~fp32-grade, routing-safe)
// MODE: 0 plain store, 1 +residual R
#define MATB 10240          // bytes per 128x32 bf16 matrix with 80B row stride
#define STAGEB (4*MATB)     // 40960 B per stage
template<int MODE>
__global__ void __launch_bounds__(256, 2)
gemm_bf3(const bf16* __restrict__ Ah_, const bf16* __restrict__ Al_,
         const bf16* __restrict__ Bh_, const bf16* __restrict__ Bl_,
         float* __restrict__ C, const float* __restrict__ R,
         int K, int lda, int ldb, int ldc) {
    extern __shared__ char smc[];
    const int bm = blockIdx.y << 7, bn = blockIdx.x << 7;
    const int tid = threadIdx.x;
    const int lane = tid & 31, w = tid >> 5;
    const int g2 = lane >> 2, t4 = lane & 3;
    const int wm = (w >> 2) << 6, wn = (w & 3) << 5;
    const int rb = tid >> 2, seg = tid & 3;      // fill: rows rb, rb+64; 16B seg
    uint32_t sbase = (uint32_t)__cvta_generic_to_shared(smc);

    auto fill = [&](int st, int k0) {            // k0 in bf16 elements
        uint32_t s0 = sbase + (uint32_t)st * STAGEB;
        const bf16* gA_h = Ah_ + (size_t)(bm + rb) * lda + k0 + seg*8;
        const bf16* gA_l = Al_ + (size_t)(bm + rb) * lda + k0 + seg*8;
        const bf16* gB_h = Bh_ + (size_t)(bn + rb) * ldb + k0 + seg*8;
        const bf16* gB_l = Bl_ + (size_t)(bn + rb) * ldb + k0 + seg*8;
        uint32_t so = (uint32_t)(rb * 80 + seg * 16);
        uint32_t so2 = so + 64u * 80u;
        size_t stride64A = (size_t)64 * lda, stride64B = (size_t)64 * ldb;
        cp16(s0 + so,              gA_h);
        cp16(s0 + so2,             gA_h + stride64A);
        cp16(s0 + MATB + so,       gA_l);
        cp16(s0 + MATB + so2,      gA_l + stride64A);
        cp16(s0 + 2*MATB + so,     gB_h);
        cp16(s0 + 2*MATB + so2,    gB_h + stride64B);
        cp16(s0 + 3*MATB + so,     gB_l);
        cp16(s0 + 3*MATB + so2,    gB_l + stride64B);
        cpcommit();
    };

    float acc[4][4][4];
#pragma unroll
    for (int i = 0; i < 4; i++)
#pragma unroll
        for (int j = 0; j < 4; j++)
#pragma unroll
            for (int q = 0; q < 4; q++) acc[i][j][q] = 0.f;

    auto compute = [&](int st) {
        uint32_t sb = sbase + (uint32_t)st * STAGEB;
#pragma unroll
        for (int kk = 0; kk < 2; kk++) {
            uint32_t ka = kk * 32u;             // 16 bf16 = 32B per k16 step
            // A fragments (hi, lo)
            uint32_t arow = (uint32_t)((wm + (lane & 15)) * 80) + ((lane >> 4) * 16) + ka;
            uint32_t ahh[4][4], ahl[4][4];
#pragma unroll
            for (int i = 0; i < 4; i++) {
                ldsm4(ahh[i], sb + arow + i * (16*80));
                ldsm4(ahl[i], sb + MATB + arow + i * (16*80));
            }
            // B fragments (hi, lo), two n8-tiles per ldmatrix.x4
            // matrices: g=0:(klo,n0-7) g=1:(khi,n0-7) g=2:(klo,n8-15) g=3:(khi,n8-15)
            uint32_t bhh[4][2], bhl[4][2];
            {
                int g = lane >> 3;
                int kblk = g & 1, rblk = g >> 1;
                uint32_t brow = (uint32_t)((wn + rblk*8 + (lane & 7)) * 80) + kblk*16 + ka;
#pragma unroll
                for (int jp = 0; jp < 2; jp++) {
                    uint32_t tmp[4];
                    ldsm4(tmp, sb + 2*MATB + brow + jp * (16*80));
                    bhh[2*jp][0]=tmp[0]; bhh[2*jp][1]=tmp[1];
                    bhh[2*jp+1][0]=tmp[2]; bhh[2*jp+1][1]=tmp[3];
                    ldsm4(tmp, sb + 3*MATB + brow + jp * (16*80));
                    bhl[2*jp][0]=tmp[0]; bhl[2*jp][1]=tmp[1];
                    bhl[2*jp+1][0]=tmp[2]; bhl[2*jp+1][1]=tmp[3];
                }
            }
#pragma unroll
            for (int i = 0; i < 4; i++)
#pragma unroll
                for (int j = 0; j < 4; j++) {
                    mma16(acc[i][j], ahh[i], bhh[j]);
                    mma16(acc[i][j], ahh[i], bhl[j]);
                    mma16(acc[i][j], ahl[i], bhh[j]);
                    mma16(acc[i][j], ahl[i], bhl[j]);
                }
        }
    };

    const int NS = K >> 5;
    fill(0, 0);
    for (int ks = 0; ks < NS; ks++) {
        cpwait<0>();
        __syncthreads();
        if (ks + 1 < NS) fill((ks + 1) & 1, (ks + 1) << 5);
        compute(ks & 1);
    }

#pragma unroll
    for (int i = 0; i < 4; i++) {
#pragma unroll
        for (int j = 0; j < 4; j++) {
            int m0 = bm + wm + 16*i + g2, m1 = m0 + 8;
            int nc = bn + wn + 8*j + 2*t4;
            float2 v0 = make_float2(acc[i][j][0], acc[i][j][1]);
            float2 v1 = make_float2(acc[i][j][2], acc[i][j][3]);
            size_t o0 = (size_t)m0 * ldc + nc, o1 = (size_t)m1 * ldc + nc;
            if (MODE == 1) {
                float2 r0 = *(const float2*)(R + o0);
                float2 r1 = *(const float2*)(R + o1);
                v0.x += r0.x; v0.y += r0.y; v1.x += r1.x; v1.y += r1.y;
            }
            *(float2*)(C + o0) = v0;
            *(float2*)(C + o1) = v1;
        }
    }
}

// ---------------- cp.async tf32 1-pass GEMM (P1 path) ---------------------
#define LDR 36
#define MATS (128*LDR)
template<int MODE>
__global__ void __launch_bounds__(256, 2)
gemm_cp(const float* __restrict__ Ah_, const float* __restrict__ Bh_,
        float* __restrict__ C, const float* __restrict__ R,
        int K, int lda, int ldb, int ldc) {
    extern __shared__ float smf[];
    const int SST = 2 * MATS;
    const int NSTAGE = 3;
    const int bm = blockIdx.y << 7, bn = blockIdx.x << 7;
    int off = 0, cnt = 0x7fffffff;
    const float* Bh = Bh_;
    if (MODE >= 2) {
        int e = blockIdx.z;
        cnt = g_cnt[e];
        if (cnt == 0 || bm >= cnt) return;
        off = g_off[e];
        Bh = Bh_ + (size_t)e * 1024 * 1024;
    }
    __shared__ int rowA[128];
    const int tid = threadIdx.x;
    if (MODE >= 2) {
        if (tid < 128) {
            int gr = bm + tid; if (gr >= cnt) gr = cnt - 1;
            rowA[tid] = (MODE == 2) ? g_ptok[off + tid + bm - bm + (gr - (bm + tid) ? 0 : 0)] : 0;
            rowA[tid] = (MODE == 2) ? g_ptok[off + gr] : (off + gr);
        }
        __syncthreads();
    }
    const int lane = tid & 31, w = tid >> 5;
    const int g2 = lane >> 2, t4 = lane & 3;
    const int wm = (w >> 2) << 6, wn = (w & 3) << 5;
    const int seg = (tid & 7) << 2, rb = tid >> 3;
    uint32_t sbase = (uint32_t)__cvta_generic_to_shared(smf);

    auto fill = [&](int st, int k0) {
        uint32_t s0 = sbase + (uint32_t)(st * SST) * 4u;
#pragma unroll
        for (int i = 0; i < 4; i++) {
            int row = rb + (i << 5);
            uint32_t so = (uint32_t)(row * LDR + seg) * 4u;
            const float* ga;
            if (MODE >= 2) ga = Ah_ + (size_t)rowA[row] * lda + k0 + seg;
            else           ga = Ah_ + (size_t)(bm + row) * lda + k0 + seg;
            cp16(s0 + so, ga);
            cp16(s0 + (uint32_t)MATS*4u + so, Bh + (size_t)(bn + row) * ldb + k0 + seg);
        }
        cpcommit();
    };

    float acc[4][4][4];
#pragma unroll
    for (int i = 0; i < 4; i++)
#pragma unroll
        for (int j = 0; j < 4; j++)
#pragma unroll
            for (int q = 0; q < 4; q++) acc[i][j][q] = 0.f;

    auto compute = [&](int st) {
        const float* SA = smf + st * SST;
        const float* SB = SA + MATS;
#pragma unroll
        for (int kb = 0; kb < 4; kb++) {
            int kc = (kb << 3) + t4;
            float ah[4][4], bh[4][2];
#pragma unroll
            for (int i = 0; i < 4; i++) {
                int m = (wm + (i << 4) + g2) * LDR;
                ah[i][0] = SA[m + kc];       ah[i][1] = SA[m + (LDR<<3) + kc];
                ah[i][2] = SA[m + kc + 4];   ah[i][3] = SA[m + (LDR<<3) + kc + 4];
            }
#pragma unroll
            for (int j = 0; j < 4; j++) {
                int n = (wn + (j << 3) + g2) * LDR;
                bh[j][0] = SB[n + kc];  bh[j][1] = SB[n + kc + 4];
            }
#pragma unroll
            for (int i = 0; i < 4; i++)
#pragma unroll
                for (int j = 0; j < 4; j++)
                    mma8(acc[i][j], ah[i][0],ah[i][1],ah[i][2],ah[i][3], bh[j][0],bh[j][1]);
        }
    };

    const int NS = K >> 5;
    fill(0, 0);
    if (NS > 1) fill(1, 32);
    for (int ks = 0; ks < NS; ks++) {
        cpwait<1>();
        __syncthreads();
        int nf = ks + NSTAGE - 1;
        if (nf < NS) fill(nf % NSTAGE, nf << 5);
        compute(ks % NSTAGE);
    }

#pragma unroll
    for (int i = 0; i < 4; i++) {
#pragma unroll
        for (int j = 0; j < 4; j++) {
            int m0 = bm + wm + 16*i + g2, m1 = m0 + 8;
            int nc = bn + wn + 8*j + 2*t4;
            float2 v0 = make_float2(acc[i][j][0], acc[i][j][1]);
            float2 v1 = make_float2(acc[i][j][2], acc[i][j][3]);
            if (MODE == 0 || MODE == 1) {
                size_t o0 = (size_t)m0 * ldc + nc, o1 = (size_t)m1 * ldc + nc;
                if (MODE == 1) {
                    float2 r0 = *(const float2*)(R + o0);
                    float2 r1 = *(const float2*)(R + o1);
                    v0.x += r0.x; v0.y += r0.y; v1.x += r1.x; v1.y += r1.y;
                }
                *(float2*)(C + o0) = v0;
                *(float2*)(C + o1) = v1;
            } else if (MODE == 2) {
                if (m0 < cnt) {
                    float2 s = make_float2(v0.x/(1.f+expf(-v0.x)), v0.y/(1.f+expf(-v0.y)));
                    *(float2*)(g_he + (size_t)(off+m0)*1024 + nc) = s;
                }
                if (m1 < cnt) {
                    float2 s = make_float2(v1.x/(1.f+expf(-v1.x)), v1.y/(1.f+expf(-v1.y)));
                    *(float2*)(g_he + (size_t)(off+m1)*1024 + nc) = s;
                }
            } else {
                if (m0 < cnt) {
                    int p = off + m0; float sc = g_pscale[p]; int d = g_pdst[p];
                    *(float2*)(g_ybuf + (size_t)d*1024 + nc) = make_float2(v0.x*sc, v0.y*sc);
                }
                if (m1 < cnt) {
                    int p = off + m1; float sc = g_pscale[p]; int d = g_pdst[p];
                    *(float2*)(g_ybuf + (size_t)d*1024 + nc) = make_float2(v1.x*sc, v1.y*sc);
                }
            }
        }
    }
}

// ---------------- flash attention: tensor-core tf32 ----------------------
#define A_LDQ 132
#define A_LDV 136
#define A_LDP 68
#define ATTN2_FLOATS (4*64*A_LDQ + 64*A_LDV + 64*A_LDP + 128 + 128 + 64 + 64)
__global__ void __launch_bounds__(256, 1) attn_tc_kernel(const float* __restrict__ q,
                                                         const float* __restrict__ kv,
                                                         bf16* __restrict__ ohi,
                                                         bf16* __restrict__ olo) {
    extern __shared__ float sm[];
    float* Qh   = sm;
    float* Ql   = Qh + 64*A_LDQ;
    float* Kh   = Ql + 64*A_LDQ;
    float* Kl   = Kh + 64*A_LDQ;
    float* Vt   = Kl + 64*A_LDQ;
    float* Ps   = Vt + 64*A_LDV;
    float* red  = Ps + 64*A_LDP;
    float* red2 = red + 128;
    float* mrow = red2 + 128;
    float* lrow = mrow + 64;

    const int qt = 15 - blockIdx.x;
    const int head = blockIdx.y, b = blockIdx.z;
    const int tid = threadIdx.x, lane = tid & 31, wid = tid >> 5;
    const int g2 = lane >> 2, t4 = lane & 3;
    const int wm = (wid & 3) << 4;
    const int wn = wid >> 2;
    const int qbase = qt << 6;
    const size_t tok0 = (size_t)b * SEQ;
    const int hoff = head << 7;

#pragma unroll
    for (int it = 0; it < 8; it++) {
        int lin = tid + (it << 8);
        int r = lin >> 5, c4 = (lin & 31) << 2;
        float4 v = *(const float4*)(q + (tok0 + qbase + r) * 1024 + hoff + c4);
        float h0 = cvt_tf32(v.x), h1 = cvt_tf32(v.y), h2 = cvt_tf32(v.z), h3 = cvt_tf32(v.w);
        *(float4*)(Qh + r*A_LDQ + c4) = make_float4(h0, h1, h2, h3);
        *(float4*)(Ql + r*A_LDQ + c4) =
            make_float4(cvt_tf32(v.x-h0), cvt_tf32(v.y-h1), cvt_tf32(v.z-h2), cvt_tf32(v.w-h3));
    }
    if (tid < 64) { mrow[tid] = -1e30f; lrow[tid] = 0.f; }

    float oacc[8][4];
#pragma unroll
    for (int j = 0; j < 8; j++)
#pragma unroll
        for (int c = 0; c < 4; c++) oacc[j][c] = 0.f;

    const int r0 = wm + g2, r1 = r0 + 8;

    for (int kt = 0; kt <= qt; kt++) {
        __syncthreads();
#pragma unroll
        for (int it = 0; it < 8; it++) {
            int lin = tid + (it << 8);
            int r = lin >> 5, c4 = (lin & 31) << 2;
            const float* krow = kv + (tok0 + (kt<<6) + r) * 2048 + hoff;
            float4 kvv = *(const float4*)(krow + c4);
            float4 vv  = *(const float4*)(krow + 1024 + c4);
            float h0 = cvt_tf32(kvv.x), h1 = cvt_tf32(kvv.y);
            float h2 = cvt_tf32(kvv.z), h3 = cvt_tf32(kvv.w);
            *(float4*)(Kh + r*A_LDQ + c4) = make_float4(h0, h1, h2, h3);
            *(float4*)(Kl + r*A_LDQ + c4) =
                make_float4(cvt_tf32(kvv.x-h0), cvt_tf32(kvv.y-h1),
                            cvt_tf32(kvv.z-h2), cvt_tf32(kvv.w-h3));
            *(float4*)(Vt + r*A_LDV + c4) =
                make_float4(cvt_tf32(vv.x), cvt_tf32(vv.y), cvt_tf32(vv.z), cvt_tf32(vv.w));
        }
        __syncthreads();
        float sacc[4][4];
#pragma unroll
        for (int j = 0; j < 4; j++)
#pragma unroll
            for (int c = 0; c < 4; c++) sacc[j][c] = 0.f;
#pragma unroll
        for (int kk = 0; kk < 16; kk++) {
            int kc = (kk << 3) + t4;
            int ar0 = r0 * A_LDQ, ar1 = r1 * A_LDQ;
            float ah0 = Qh[ar0+kc], ah1 = Qh[ar1+kc], ah2 = Qh[ar0+kc+4], ah3 = Qh[ar1+kc+4];
            float al0 = Ql[ar0+kc], al1 = Ql[ar1+kc], al2 = Ql[ar0+kc+4], al3 = Ql[ar1+kc+4];
#pragma unroll
            for (int j = 0; j < 4; j++) {
                int br = ((wn<<5) + (j<<3) + g2) * A_LDQ;
                float bh0 = Kh[br+kc], bh1 = Kh[br+kc+4];
                float bl0 = Kl[br+kc], bl1 = Kl[br+kc+4];
                mma8(sacc[j], ah0, ah1, ah2, ah3, bh0, bh1);
                mma8(sacc[j], ah0, ah1, ah2, ah3, bl0, bl1);
                mma8(sacc[j], al0, al1, al2, al3, bh0, bh1);
            }
        }
#pragma unroll
        for (int j = 0; j < 4; j++)
#pragma unroll
            for (int c = 0; c < 4; c++) sacc[j][c] *= SCALE_F;
        if (kt == qt) {
            int grow0 = qbase + r0, grow1 = qbase + r1;
#pragma unroll
            for (int j = 0; j < 4; j++) {
                int col = (kt<<6) + (wn<<5) + (j<<3) + (t4<<1);
                if (col   > grow0) sacc[j][0] = -1e30f;
                if (col+1 > grow0) sacc[j][1] = -1e30f;
                if (col   > grow1) sacc[j][2] = -1e30f;
                if (col+1 > grow1) sacc[j][3] = -1e30f;
            }
        }
        float mx0 = fmaxf(fmaxf(sacc[0][0], sacc[0][1]), fmaxf(sacc[1][0], sacc[1][1]));
        mx0 = fmaxf(mx0, fmaxf(fmaxf(sacc[2][0], sacc[2][1]), fmaxf(sacc[3][0], sacc[3][1])));
        float mx1 = fmaxf(fmaxf(sacc[0][2], sacc[0][3]), fmaxf(sacc[1][2], sacc[1][3]));
        mx1 = fmaxf(mx1, fmaxf(fmaxf(sacc[2][2], sacc[2][3]), fmaxf(sacc[3][2], sacc[3][3])));
        mx0 = fmaxf(mx0, __shfl_xor_sync(0xffffffffu, mx0, 1));
        mx0 = fmaxf(mx0, __shfl_xor_sync(0xffffffffu, mx0, 2));
        mx1 = fmaxf(mx1, __shfl_xor_sync(0xffffffffu, mx1, 1));
        mx1 = fmaxf(mx1, __shfl_xor_sync(0xffffffffu, mx1, 2));
        if (t4 == 0) { red[(r0<<1) + wn] = mx0; red[(r1<<1) + wn] = mx1; }
        __syncthreads();
        float mo0 = mrow[r0], mo1 = mrow[r1];
        float mn0 = fmaxf(mo0, fmaxf(red[r0<<1], red[(r0<<1)+1]));
        float mn1 = fmaxf(mo1, fmaxf(red[r1<<1], red[(r1<<1)+1]));
        float f0 = __expf(mo0 - mn0), f1 = __expf(mo1 - mn1);
        float ps0 = 0.f, ps1 = 0.f;
#pragma unroll
        for (int j = 0; j < 4; j++) {
            float p0 = __expf(sacc[j][0] - mn0), p1 = __expf(sacc[j][1] - mn0);
            float p2 = __expf(sacc[j][2] - mn1), p3 = __expf(sacc[j][3] - mn1);
            ps0 += p0 + p1; ps1 += p2 + p3;
            int pc = (wn<<5) + (j<<3) + (t4<<1);
            *(float2*)(Ps + r0*A_LDP + pc) = make_float2(cvt_tf32(p0), cvt_tf32(p1));
            *(float2*)(Ps + r1*A_LDP + pc) = make_float2(cvt_tf32(p2), cvt_tf32(p3));
        }
        ps0 += __shfl_xor_sync(0xffffffffu, ps0, 1);
        ps0 += __shfl_xor_sync(0xffffffffu, ps0, 2);
        ps1 += __shfl_xor_sync(0xffffffffu, ps1, 1);
        ps1 += __shfl_xor_sync(0xffffffffu, ps1, 2);
        if (t4 == 0) { red2[(r0<<1) + wn] = ps0; red2[(r1<<1) + wn] = ps1; }
#pragma unroll
        for (int j = 0; j < 8; j++) {
            oacc[j][0] *= f0; oacc[j][1] *= f0;
            oacc[j][2] *= f1; oacc[j][3] *= f1;
        }
        __syncthreads();
        if (wn == 0 && t4 == 0) {
            mrow[r0] = mn0; lrow[r0] = lrow[r0] * f0 + red2[r0<<1] + red2[(r0<<1)+1];
            mrow[r1] = mn1; lrow[r1] = lrow[r1] * f1 + red2[r1<<1] + red2[(r1<<1)+1];
        }
#pragma unroll
        for (int kk = 0; kk < 8; kk++) {
            int kc = (kk << 3) + t4;
            float a0 = Ps[r0*A_LDP + kc], a1 = Ps[r1*A_LDP + kc];
            float a2 = Ps[r0*A_LDP + kc + 4], a3 = Ps[r1*A_LDP + kc + 4];
#pragma unroll
            for (int j = 0; j < 8; j++) {
                int bc = (wn<<6) + (j<<3) + g2;
                float b0 = Vt[kc*A_LDV + bc];
                float b1 = Vt[(kc+4)*A_LDV + bc];
                mma8(oacc[j], a0, a1, a2, a3, b0, b1);
            }
        }
    }
    __syncthreads();
    float il0 = 1.f / lrow[r0], il1 = 1.f / lrow[r1];
#pragma unroll
    for (int j = 0; j < 8; j++) {
        int col = hoff + (wn<<6) + (j<<3) + (t4<<1);
        size_t o0 = (tok0 + qbase + r0) * 1024 + col;
        size_t o1 = (tok0 + qbase + r1) * 1024 + col;
        float v00 = oacc[j][0]*il0, v01 = oacc[j][1]*il0;
        float v10 = oacc[j][2]*il1, v11 = oacc[j][3]*il1;
        float h00 = __bfloat162float(__float2bfloat16_rn(v00));
        float h01 = __bfloat162float(__float2bfloat16_rn(v01));
        float h10 = __bfloat162float(__float2bfloat16_rn(v10));
        float h11 = __bfloat162float(__float2bfloat16_rn(v11));
        *(uint32_t*)(ohi + o0) = packbf2(h00, h01);
        *(uint32_t*)(ohi + o1) = packbf2(h10, h11);
        *(uint32_t*)(olo + o0) = packbf2(v00-h00, v01-h01);
        *(uint32_t*)(olo + o1) = packbf2(v10-h10, v11-h11);
    }
}

// ---------------- MoE gate ---------------
__global__ void gate_kernel(const float* __restrict__ h2, const float* __restrict__ gw) {
    int t = blockIdx.x;
    int w = threadIdx.x >> 5, lane = threadIdx.x & 31;
    const float* xr = h2 + (size_t)t * HD;
    const float* gr = gw + (size_t)w * HD;
    float ss = 0.f;
    for (int i = lane; i < HD; i += 32) ss += xr[i] * gr[i];
#pragma unroll
    for (int o = 16; o > 0; o >>= 1) ss += __shfl_down_sync(0xffffffffu, ss, o);
    __shared__ float lg[NEXP];
    if (lane == 0) lg[w] = ss;
    __syncthreads();
    if (threadIdx.x == 0) {
        int i1 = 0;
#pragma unroll
        for (int e = 1; e < NEXP; e++) if (lg[e] > lg[i1]) i1 = e;
        int i2 = (i1 == 0) ? 1 : 0;
#pragma unroll
        for (int e = 0; e < NEXP; e++) if (e != i1 && lg[e] > lg[i2]) i2 = e;
        float e2 = expf(lg[i2] - lg[i1]);
        float inv = 1.f / (1.f + e2);
        g_topi[2*t]   = i1; g_topw[2*t]   = inv;
        g_topi[2*t+1] = i2; g_topw[2*t+1] = e2 * inv;
    }
}

// ---------------- deterministic expert grouping --------------------------
__global__ void route_group_kernel() {
    __shared__ int hist[NEXP * 256];
    __shared__ int soff[NEXP + 1];
    __shared__ int stot[NEXP];
    int tid = threadIdx.x;
    int t0 = tid * 8;
    int lc[NEXP];
#pragma unroll
    for (int e = 0; e < NEXP; e++) lc[e] = 0;
    for (int t = t0; t < t0 + 8; t++) {
        lc[g_topi[2*t]]++; lc[g_topi[2*t+1]]++;
    }
#pragma unroll
    for (int e = 0; e < NEXP; e++) hist[e * 256 + tid] = lc[e];
    __syncthreads();
    if (tid < NEXP) {
        int a = 0;
        for (int i = 0; i < 256; i++) { int v = hist[tid*256+i]; hist[tid*256+i] = a; a += v; }
        stot[tid] = a;
    }
    __syncthreads();
    if (tid == 0) {
        int a = 0;
        for (int e = 0; e < NEXP; e++) { soff[e] = a; g_off[e] = a; g_cnt[e] = stot[e]; a += stot[e]; }
        soff[NEXP] = a;
    }
    __syncthreads();
    int pos[NEXP];
#pragma unroll
    for (int e = 0; e < NEXP; e++) pos[e] = soff[e] + hist[e * 256 + tid];
    for (int t = t0; t < t0 + 8; t++) {
        for (int s2 = 0; s2 < 2; s2++) {
            int e = g_topi[2*t + s2];
            int p = pos[e]++;
            g_ptok[p] = t; g_pdst[p] = 2*t + s2; g_pscale[p] = g_topw[2*t + s2];
        }
    }
}

// ---------------- elementwise tails --------------------------------------
__global__ void swiglu_kernel(const float* __restrict__ gu, float* __restrict__ act) {
    int t = blockIdx.x, i = threadIdx.x;
    float4 g = *(const float4*)(gu + (size_t)t*2048 + 4*i);
    float4 u = *(const float4*)(gu + (size_t)t*2048 + 1024 + 4*i);
    float4 r;
    r.x = g.x / (1.f + expf(-g.x)) * u.x;
    r.y = g.y / (1.f + expf(-g.y)) * u.y;
    r.z = g.z / (1.f + expf(-g.z)) * u.z;
    r.w = g.w / (1.f + expf(-g.w)) * u.w;
    *(float4*)(act + (size_t)t*HD + 4*i) = r;
}

__global__ void add_routed_kernel(float* __restrict__ out) {
    int t = blockIdx.x, i = threadIdx.x;
    float4 a = *(const float4*)(out + (size_t)t*HD + 4*i);
    float4 y0 = *(const float4*)(g_ybuf + (size_t)(2*t)*HD + 4*i);
    float4 y1 = *(const float4*)(g_ybuf + (size_t)(2*t+1)*HD + 4*i);
    a.x += y0.x + y1.x; a.y += y0.y + y1.y; a.z += y0.z + y1.z; a.w += y0.w + y1.w;
    *(float4*)(out + (size_t)t*HD + 4*i) = a;
}

// ---------------- launch ---------------------------------------------------
extern "C" void kernel_launch(void* const* d_in, const int* in_sizes, int n_in,
                              void* d_out, int out_size) {
    const float* x    = (const float*)d_in[0];
    const float* ln1  = (const float*)d_in[2];
    const float* ln2  = (const float*)d_in[3];
    const float* Wq   = (const float*)d_in[4];
    const float* Wkv  = (const float*)d_in[5];
    const float* Wo   = (const float*)d_in[6];
    const float* gate = (const float*)d_in[7];
    const float* w1   = (const float*)d_in[8];
    const float* w2   = (const float*)d_in[9];
    const float* sgu  = (const float*)d_in[10];
    const float* sdwn = (const float*)d_in[11];
    float* out = (float*)d_out;

    bf16 *p_wq_hi,*p_wq_lo,*p_wkv_hi,*p_wkv_lo,*p_wo_hi,*p_wo_lo;
    bf16 *p_h_hi,*p_h_lo,*p_o_hi,*p_o_lo;
    float *p_q,*p_kv,*p_x2,*p_h2,*p_gu,*p_act,*p_he;
    cudaGetSymbolAddress((void**)&p_wq_hi,  g_wq_hi);
    cudaGetSymbolAddress((void**)&p_wq_lo,  g_wq_lo);
    cudaGetSymbolAddress((void**)&p_wkv_hi, g_wkv_hi);
    cudaGetSymbolAddress((void**)&p_wkv_lo, g_wkv_lo);
    cudaGetSymbolAddress((void**)&p_wo_hi,  g_wo_hi);
    cudaGetSymbolAddress((void**)&p_wo_lo,  g_wo_lo);
    cudaGetSymbolAddress((void**)&p_h_hi,   g_h_hi);
    cudaGetSymbolAddress((void**)&p_h_lo,   g_h_lo);
    cudaGetSymbolAddress((void**)&p_o_hi,   g_o_hi);
    cudaGetSymbolAddress((void**)&p_o_lo,   g_o_lo);
    cudaGetSymbolAddress((void**)&p_q,      g_q);
    cudaGetSymbolAddress((void**)&p_kv,     g_kv);
    cudaGetSymbolAddress((void**)&p_x2,     g_x2);
    cudaGetSymbolAddress((void**)&p_h2,     g_h2);
    cudaGetSymbolAddress((void**)&p_gu,     g_gu);
    cudaGetSymbolAddress((void**)&p_act,    g_act);
    cudaGetSymbolAddress((void**)&p_he,     g_he);

    const int ATTN2_SMEM = ATTN2_FLOATS * 4;
    cudaFuncSetAttribute(attn_tc_kernel, cudaFuncAttributeMaxDynamicSharedMemorySize, ATTN2_SMEM);
    const int SM_P1 = 3 * 2 * MATS * 4;   // 110592 B (3-stage tf32)
    const int SM_BF = 2 * STAGEB;         // 81920 B (2-stage bf16 4-mat)
    cudaFuncSetAttribute(gemm_bf3<0>, cudaFuncAttributeMaxDynamicSharedMemorySize, SM_BF);
    cudaFuncSetAttribute(gemm_bf3<1>, cudaFuncAttributeMaxDynamicSharedMemorySize, SM_BF);
    cudaFuncSetAttribute(gemm_cp<0>, cudaFuncAttributeMaxDynamicSharedMemorySize, SM_P1);
    cudaFuncSetAttribute(gemm_cp<1>, cudaFuncAttributeMaxDynamicSharedMemorySize, SM_P1);
    cudaFuncSetAttribute(gemm_cp<2>, cudaFuncAttributeMaxDynamicSharedMemorySize, SM_P1);
    cudaFuncSetAttribute(gemm_cp<3>, cudaFuncAttributeMaxDynamicSharedMemorySize, SM_P1);

    // weight bf16 hi/lo splits for routing-critical GEMMs
    pack_wq_kernel<<<1024, 256>>>(Wq, p_wq_hi, p_wq_lo);
    split_kernel<<<2048, 256>>>(Wkv, p_wkv_hi, p_wkv_lo);
    split_kernel<<<1024, 256>>>(Wo, p_wo_hi, p_wo_lo);

    // attention block (bf16 4-pass = routing-safe precision)
    rmsnorm_kernel<1><<<TT, 256>>>(x, ln1, p_h_hi, p_h_lo);
    gemm_bf3<0><<<dim3(8, 16), 256, SM_BF>>>(p_h_hi, p_h_lo, p_wq_hi, p_wq_lo,
                                             p_q, nullptr, 1024, 1024, 1024, 1024);
    gemm_bf3<0><<<dim3(16,16), 256, SM_BF>>>(p_h_hi, p_h_lo, p_wkv_hi, p_wkv_lo,
                                             p_kv, nullptr, 1024, 1024, 1024, 2048);
    attn_tc_kernel<<<dim3(16, NH, 2), 256, ATTN2_SMEM>>>(p_q, p_kv, p_o_hi, p_o_lo);
    gemm_bf3<1><<<dim3(8, 16), 256, SM_BF>>>(p_o_hi, p_o_lo, p_wo_hi, p_wo_lo,
                                             p_x2, x, 1024, 1024, 1024, 1024);

    // MoE block
    rmsnorm_kernel<0><<<TT, 256>>>(p_x2, ln2, p_h2, nullptr);
    gate_kernel<<<TT, 256>>>(p_h2, gate);
    route_group_kernel<<<1, 256>>>();
    gemm_cp<2><<<dim3(8, 32, NEXP), 256, SM_P1>>>(p_h2, w1, nullptr, nullptr,
                                                  1024, 1024, 1024, 1024);
    gemm_cp<3><<<dim3(8, 32, NEXP), 256, SM_P1>>>(p_he, w2, nullptr, nullptr,
                                                  1024, 1024, 1024, 1024);

    // shared expert
    gemm_cp<0><<<dim3(16,16), 256, SM_P1>>>(p_h2, sgu, p_gu, nullptr,
                                            1024, 1024, 1024, 2048);
    swiglu_kernel<<<TT, 256>>>(p_gu, p_act);
    gemm_cp<1><<<dim3(8, 16), 256, SM_P1>>>(p_act, sdwn, out, p_x2,
                                            1024, 1024, 1024, 1024);

    // combine routed experts
    add_routed_kernel<<<TT, 256>>>(out);
}

// round 11
// speedup vs baseline: 1.3483x; 1.1137x over previous
#include <cuda_runtime.h>
#include <cuda_bf16.h>
#include <stdint.h>
#include <math.h>

#define TT    2048
#define HD    1024
#define NH    8
#define SEQ   1024
#define NEXP  8
#define SCALE_F 0.07216878364870322f   // 192^-0.5

typedef __nv_bfloat16 bf16;

// ---------------- scratch ----------------
__device__ bf16  g_wq_hi [1024*1024];
__device__ bf16  g_wq_lo [1024*1024];
__device__ bf16  g_wkv_hi[2048*1024];
__device__ bf16  g_wkv_lo[2048*1024];
__device__ bf16  g_wo_hi [1024*1024];
__device__ bf16  g_wo_lo [1024*1024];
__device__ bf16  g_h_hi  [TT*HD];
__device__ bf16  g_h_lo  [TT*HD];
__device__ bf16  g_o_hi  [TT*1024];
__device__ bf16  g_o_lo  [TT*1024];
__device__ float g_q     [TT*1024];
__device__ float g_kv    [TT*2048];
__device__ float g_x2    [TT*HD];
__device__ float g_h2    [TT*HD];
__device__ float g_gu    [TT*2048];
__device__ float g_act   [TT*1024];
__device__ float g_he    [2*TT*1024];
__device__ float g_ybuf  [2*TT*1024];
__device__ float g_topw  [2*TT];
__device__ float g_pscale[2*TT];
__device__ int   g_topi[2*TT];
__device__ int   g_ptok[2*TT];
__device__ int   g_pdst[2*TT];
__device__ int   g_cnt [NEXP];
__device__ int   g_off [NEXP];

// ---------------- helpers ----------------
__device__ __forceinline__ float cvt_tf32(float x) {
    unsigned u; asm("cvt.rna.tf32.f32 %0, %1;" : "=r"(u) : "f"(x));
    return __uint_as_float(u);
}
__device__ __forceinline__ void mma8(float* d, float a0, float a1, float a2, float a3,
                                     float b0, float b1) {
    unsigned A0=__float_as_uint(a0), A1=__float_as_uint(a1);
    unsigned A2=__float_as_uint(a2), A3=__float_as_uint(a3);
    unsigned B0=__float_as_uint(b0), B1=__float_as_uint(b1);
    asm volatile("mma.sync.aligned.m16n8k8.row.col.f32.tf32.tf32.f32 "
                 "{%0,%1,%2,%3},{%4,%5,%6,%7},{%8,%9},{%0,%1,%2,%3};"
                 : "+f"(d[0]), "+f"(d[1]), "+f"(d[2]), "+f"(d[3])
                 : "r"(A0), "r"(A1), "r"(A2), "r"(A3), "r"(B0), "r"(B1));
}
__device__ __forceinline__ void mma16(float* d, const uint32_t* a, const uint32_t* b) {
    asm volatile("mma.sync.aligned.m16n8k16.row.col.f32.bf16.bf16.f32 "
                 "{%0,%1,%2,%3},{%4,%5,%6,%7},{%8,%9},{%0,%1,%2,%3};"
                 : "+f"(d[0]), "+f"(d[1]), "+f"(d[2]), "+f"(d[3])
                 : "r"(a[0]), "r"(a[1]), "r"(a[2]), "r"(a[3]), "r"(b[0]), "r"(b[1]));
}
__device__ __forceinline__ void ldsm4(uint32_t* r, uint32_t a) {
    asm volatile("ldmatrix.sync.aligned.m8n8.x4.shared.b16 {%0,%1,%2,%3}, [%4];"
                 : "=r"(r[0]), "=r"(r[1]), "=r"(r[2]), "=r"(r[3]) : "r"(a));
}
__device__ __forceinline__ void cp16(uint32_t s, const void* g) {
    asm volatile("cp.async.cg.shared.global [%0], [%1], 16;" :: "r"(s), "l"(g));
}
__device__ __forceinline__ void cpcommit() { asm volatile("cp.async.commit_group;"); }
template<int N> __device__ __forceinline__ void cpwait() {
    asm volatile("cp.async.wait_group %0;" :: "n"(N));
}
__device__ __forceinline__ uint32_t packbf2(float a, float b) {
    __nv_bfloat162 t = __floats2bfloat162_rn(a, b);
    return *(uint32_t*)&t;
}

// ---------------- pack Wq (nope rows only) + bf16 hi/lo split -------------
__global__ void pack_wq_kernel(const float* __restrict__ Wq,
                               bf16* __restrict__ hi, bf16* __restrict__ lo) {
    int r = blockIdx.x;
    int h = r >> 7, d = r & 127;
    float4 v = ((const float4*)(Wq + (size_t)(h*192 + d) * HD))[threadIdx.x];
    float h0 = __bfloat162float(__float2bfloat16_rn(v.x));
    float h1 = __bfloat162float(__float2bfloat16_rn(v.y));
    float h2 = __bfloat162float(__float2bfloat16_rn(v.z));
    float h3 = __bfloat162float(__float2bfloat16_rn(v.w));
    uint2 ph = make_uint2(packbf2(h0, h1), packbf2(h2, h3));
    uint2 pl = make_uint2(packbf2(v.x-h0, v.y-h1), packbf2(v.z-h2, v.w-h3));
    ((uint2*)(hi + (size_t)r * HD))[threadIdx.x] = ph;
    ((uint2*)(lo + (size_t)r * HD))[threadIdx.x] = pl;
}

// ---------------- generic bf16 hi/lo split --------------------------------
__global__ void split_kernel(const float* __restrict__ src,
                             bf16* __restrict__ hi, bf16* __restrict__ lo) {
    size_t i = ((size_t)blockIdx.x * 256 + threadIdx.x);
    float4 v = ((const float4*)src)[i];
    float h0 = __bfloat162float(__float2bfloat16_rn(v.x));
    float h1 = __bfloat162float(__float2bfloat16_rn(v.y));
    float h2 = __bfloat162float(__float2bfloat16_rn(v.z));
    float h3 = __bfloat162float(__float2bfloat16_rn(v.w));
    ((uint2*)hi)[i] = make_uint2(packbf2(h0, h1), packbf2(h2, h3));
    ((uint2*)lo)[i] = make_uint2(packbf2(v.x-h0, v.y-h1), packbf2(v.z-h2, v.w-h3));
}

// ---------------- rmsnorm (SPLIT=1: bf16 hi/lo; 0: fp32) ------------------
template<int SPLIT>
__global__ void rmsnorm_kernel(const float* __restrict__ x, const float* __restrict__ w,
                               void* __restrict__ out, bf16* __restrict__ out_lo) {
    int t = blockIdx.x;
    float4 v = ((const float4*)(x + (size_t)t * HD))[threadIdx.x];
    float ss = v.x*v.x + v.y*v.y + v.z*v.z + v.w*v.w;
    __shared__ float red[256];
    red[threadIdx.x] = ss; __syncthreads();
    for (int o = 128; o > 0; o >>= 1) {
        if (threadIdx.x < o) red[threadIdx.x] += red[threadIdx.x + o];
        __syncthreads();
    }
    float inv = rsqrtf(red[0] * (1.f / HD) + 1e-6f);
    float4 wv = ((const float4*)w)[threadIdx.x];
    float o0 = v.x*inv*wv.x, o1 = v.y*inv*wv.y, o2 = v.z*inv*wv.z, o3 = v.w*inv*wv.w;
    if (SPLIT) {
        float h0 = __bfloat162float(__float2bfloat16_rn(o0));
        float h1 = __bfloat162float(__float2bfloat16_rn(o1));
        float h2 = __bfloat162float(__float2bfloat16_rn(o2));
        float h3 = __bfloat162float(__float2bfloat16_rn(o3));
        ((uint2*)((bf16*)out + (size_t)t * HD))[threadIdx.x] =
            make_uint2(packbf2(h0, h1), packbf2(h2, h3));
        ((uint2*)(out_lo + (size_t)t * HD))[threadIdx.x] =
            make_uint2(packbf2(o0-h0, o1-h1), packbf2(o2-h2, o3-h3));
    } else {
        ((float4*)((float*)out + (size_t)t * HD))[threadIdx.x] = make_float4(o0, o1, o2, o3);
    }
}

// ---------------- bf16 3-pass GEMM (NT), ldmatrix + cp.async --------------
// C = Ahi*Bhi + Ahi*Blo + Alo*Bhi   (lo*lo dropped: ~2^-18 rel, negligible)
// MODE: 0 plain store, 1 +residual R
#define MATB 10240          // bytes per 128x32 bf16 matrix with 80B row stride
#define STAGEB (4*MATB)     // 40960 B per stage
template<int MODE>
__global__ void __launch_bounds__(256, 2)
gemm_bf3(const bf16* __restrict__ Ah_, const bf16* __restrict__ Al_,
         const bf16* __restrict__ Bh_, const bf16* __restrict__ Bl_,
         float* __restrict__ C, const float* __restrict__ R,
         int K, int lda, int ldb, int ldc) {
    extern __shared__ char smc[];
    const int bm = blockIdx.y << 7, bn = blockIdx.x << 7;
    const int tid = threadIdx.x;
    const int lane = tid & 31, w = tid >> 5;
    const int g2 = lane >> 2, t4 = lane & 3;
    const int wm = (w >> 2) << 6, wn = (w & 3) << 5;
    const int rb = tid >> 2, seg = tid & 3;
    uint32_t sbase = (uint32_t)__cvta_generic_to_shared(smc);

    auto fill = [&](int st, int k0) {
        uint32_t s0 = sbase + (uint32_t)st * STAGEB;
        const bf16* gA_h = Ah_ + (size_t)(bm + rb) * lda + k0 + seg*8;
        const bf16* gA_l = Al_ + (size_t)(bm + rb) * lda + k0 + seg*8;
        const bf16* gB_h = Bh_ + (size_t)(bn + rb) * ldb + k0 + seg*8;
        const bf16* gB_l = Bl_ + (size_t)(bn + rb) * ldb + k0 + seg*8;
        uint32_t so = (uint32_t)(rb * 80 + seg * 16);
        uint32_t so2 = so + 64u * 80u;
        size_t stride64A = (size_t)64 * lda, stride64B = (size_t)64 * ldb;
        cp16(s0 + so,              gA_h);
        cp16(s0 + so2,             gA_h + stride64A);
        cp16(s0 + MATB + so,       gA_l);
        cp16(s0 + MATB + so2,      gA_l + stride64A);
        cp16(s0 + 2*MATB + so,     gB_h);
        cp16(s0 + 2*MATB + so2,    gB_h + stride64B);
        cp16(s0 + 3*MATB + so,     gB_l);
        cp16(s0 + 3*MATB + so2,    gB_l + stride64B);
        cpcommit();
    };

    float acc[4][4][4];
#pragma unroll
    for (int i = 0; i < 4; i++)
#pragma unroll
        for (int j = 0; j < 4; j++)
#pragma unroll
            for (int q = 0; q < 4; q++) acc[i][j][q] = 0.f;

    auto compute = [&](int st) {
        uint32_t sb = sbase + (uint32_t)st * STAGEB;
#pragma unroll
        for (int kk = 0; kk < 2; kk++) {
            uint32_t ka = kk * 32u;
            uint32_t arow = (uint32_t)((wm + (lane & 15)) * 80) + ((lane >> 4) * 16) + ka;
            uint32_t ahh[4][4], ahl[4][4];
#pragma unroll
            for (int i = 0; i < 4; i++) {
                ldsm4(ahh[i], sb + arow + i * (16*80));
                ldsm4(ahl[i], sb + MATB + arow + i * (16*80));
            }
            uint32_t bhh[4][2], bhl[4][2];
            {
                int g = lane >> 3;
                int kblk = g & 1, rblk = g >> 1;
                uint32_t brow = (uint32_t)((wn + rblk*8 + (lane & 7)) * 80) + kblk*16 + ka;
#pragma unroll
                for (int jp = 0; jp < 2; jp++) {
                    uint32_t tmp[4];
                    ldsm4(tmp, sb + 2*MATB + brow + jp * (16*80));
                    bhh[2*jp][0]=tmp[0]; bhh[2*jp][1]=tmp[1];
                    bhh[2*jp+1][0]=tmp[2]; bhh[2*jp+1][1]=tmp[3];
                    ldsm4(tmp, sb + 3*MATB + brow + jp * (16*80));
                    bhl[2*jp][0]=tmp[0]; bhl[2*jp][1]=tmp[1];
                    bhl[2*jp+1][0]=tmp[2]; bhl[2*jp+1][1]=tmp[3];
                }
            }
#pragma unroll
            for (int i = 0; i < 4; i++)
#pragma unroll
                for (int j = 0; j < 4; j++) {
                    mma16(acc[i][j], ahh[i], bhh[j]);
                    mma16(acc[i][j], ahh[i], bhl[j]);
                    mma16(acc[i][j], ahl[i], bhh[j]);
                }
        }
    };

    const int NS = K >> 5;
    fill(0, 0);
    for (int ks = 0; ks < NS; ks++) {
        cpwait<0>();
        __syncthreads();
        if (ks + 1 < NS) fill((ks + 1) & 1, (ks + 1) << 5);
        compute(ks & 1);
    }

#pragma unroll
    for (int i = 0; i < 4; i++) {
#pragma unroll
        for (int j = 0; j < 4; j++) {
            int m0 = bm + wm + 16*i + g2, m1 = m0 + 8;
            int nc = bn + wn + 8*j + 2*t4;
            float2 v0 = make_float2(acc[i][j][0], acc[i][j][1]);
            float2 v1 = make_float2(acc[i][j][2], acc[i][j][3]);
            size_t o0 = (size_t)m0 * ldc + nc, o1 = (size_t)m1 * ldc + nc;
            if (MODE == 1) {
                float2 r0 = *(const float2*)(R + o0);
                float2 r1 = *(const float2*)(R + o1);
                v0.x += r0.x; v0.y += r0.y; v1.x += r1.x; v1.y += r1.y;
            }
            *(float2*)(C + o0) = v0;
            *(float2*)(C + o1) = v1;
        }
    }
}

// ---------------- cp.async tf32 1-pass GEMM (P1 path) ---------------------
#define LDR 36
#define MATS (128*LDR)
template<int MODE>
__global__ void __launch_bounds__(256, 2)
gemm_cp(const float* __restrict__ Ah_, const float* __restrict__ Bh_,
        float* __restrict__ C, const float* __restrict__ R,
        int K, int lda, int ldb, int ldc) {
    extern __shared__ float smf[];
    const int SST = 2 * MATS;
    const int NSTAGE = 3;
    const int bm = blockIdx.y << 7, bn = blockIdx.x << 7;
    int off = 0, cnt = 0x7fffffff;
    const float* Bh = Bh_;
    if (MODE >= 2) {
        int e = blockIdx.z;
        cnt = g_cnt[e];
        if (cnt == 0 || bm >= cnt) return;
        off = g_off[e];
        Bh = Bh_ + (size_t)e * 1024 * 1024;
    }
    __shared__ int rowA[128];
    const int tid = threadIdx.x;
    if (MODE >= 2) {
        if (tid < 128) {
            int gr = bm + tid; if (gr >= cnt) gr = cnt - 1;
            rowA[tid] = (MODE == 2) ? g_ptok[off + gr] : (off + gr);
        }
        __syncthreads();
    }
    const int lane = tid & 31, w = tid >> 5;
    const int g2 = lane >> 2, t4 = lane & 3;
    const int wm = (w >> 2) << 6, wn = (w & 3) << 5;
    const int seg = (tid & 7) << 2, rb = tid >> 3;
    uint32_t sbase = (uint32_t)__cvta_generic_to_shared(smf);

    auto fill = [&](int st, int k0) {
        uint32_t s0 = sbase + (uint32_t)(st * SST) * 4u;
#pragma unroll
        for (int i = 0; i < 4; i++) {
            int row = rb + (i << 5);
            uint32_t so = (uint32_t)(row * LDR + seg) * 4u;
            const float* ga;
            if (MODE >= 2) ga = Ah_ + (size_t)rowA[row] * lda + k0 + seg;
            else           ga = Ah_ + (size_t)(bm + row) * lda + k0 + seg;
            cp16(s0 + so, ga);
            cp16(s0 + (uint32_t)MATS*4u + so, Bh + (size_t)(bn + row) * ldb + k0 + seg);
        }
        cpcommit();
    };

    float acc[4][4][4];
#pragma unroll
    for (int i = 0; i < 4; i++)
#pragma unroll
        for (int j = 0; j < 4; j++)
#pragma unroll
            for (int q = 0; q < 4; q++) acc[i][j][q] = 0.f;

    auto compute = [&](int st) {
        const float* SA = smf + st * SST;
        const float* SB = SA + MATS;
#pragma unroll
        for (int kb = 0; kb < 4; kb++) {
            int kc = (kb << 3) + t4;
            float ah[4][4], bh[4][2];
#pragma unroll
            for (int i = 0; i < 4; i++) {
                int m = (wm + (i << 4) + g2) * LDR;
                ah[i][0] = SA[m + kc];       ah[i][1] = SA[m + (LDR<<3) + kc];
                ah[i][2] = SA[m + kc + 4];   ah[i][3] = SA[m + (LDR<<3) + kc + 4];
            }
#pragma unroll
            for (int j = 0; j < 4; j++) {
                int n = (wn + (j << 3) + g2) * LDR;
                bh[j][0] = SB[n + kc];  bh[j][1] = SB[n + kc + 4];
            }
#pragma unroll
            for (int i = 0; i < 4; i++)
#pragma unroll
                for (int j = 0; j < 4; j++)
                    mma8(acc[i][j], ah[i][0],ah[i][1],ah[i][2],ah[i][3], bh[j][0],bh[j][1]);
        }
    };

    const int NS = K >> 5;
    fill(0, 0);
    if (NS > 1) fill(1, 32);
    for (int ks = 0; ks < NS; ks++) {
        cpwait<1>();
        __syncthreads();
        int nf = ks + NSTAGE - 1;
        if (nf < NS) fill(nf % NSTAGE, nf << 5);
        compute(ks % NSTAGE);
    }

#pragma unroll
    for (int i = 0; i < 4; i++) {
#pragma unroll
        for (int j = 0; j < 4; j++) {
            int m0 = bm + wm + 16*i + g2, m1 = m0 + 8;
            int nc = bn + wn + 8*j + 2*t4;
            float2 v0 = make_float2(acc[i][j][0], acc[i][j][1]);
            float2 v1 = make_float2(acc[i][j][2], acc[i][j][3]);
            if (MODE == 0 || MODE == 1) {
                size_t o0 = (size_t)m0 * ldc + nc, o1 = (size_t)m1 * ldc + nc;
                if (MODE == 1) {
                    float2 r0 = *(const float2*)(R + o0);
                    float2 r1 = *(const float2*)(R + o1);
                    v0.x += r0.x; v0.y += r0.y; v1.x += r1.x; v1.y += r1.y;
                }
                *(float2*)(C + o0) = v0;
                *(float2*)(C + o1) = v1;
            } else if (MODE == 2) {
                if (m0 < cnt) {
                    float2 s = make_float2(v0.x/(1.f+expf(-v0.x)), v0.y/(1.f+expf(-v0.y)));
                    *(float2*)(g_he + (size_t)(off+m0)*1024 + nc) = s;
                }
                if (m1 < cnt) {
                    float2 s = make_float2(v1.x/(1.f+expf(-v1.x)), v1.y/(1.f+expf(-v1.y)));
                    *(float2*)(g_he + (size_t)(off+m1)*1024 + nc) = s;
                }
            } else {
                if (m0 < cnt) {
                    int p = off + m0; float sc = g_pscale[p]; int d = g_pdst[p];
                    *(float2*)(g_ybuf + (size_t)d*1024 + nc) = make_float2(v0.x*sc, v0.y*sc);
                }
                if (m1 < cnt) {
                    int p = off + m1; float sc = g_pscale[p]; int d = g_pdst[p];
                    *(float2*)(g_ybuf + (size_t)d*1024 + nc) = make_float2(v1.x*sc, v1.y*sc);
                }
            }
        }
    }
}

// ---------------- flash attention: QK bf16 3-pass + PV tf32 ---------------
#define A_KB   272
#define A_QHB  0
#define A_QLB  17408
#define A_KHB  34816
#define A_KLB  52224
#define A_VT   69632
#define A_PS   104448
#define A_RED  121856
#define A_LDV 136
#define A_LDP 68
#define ATTN3_BYTES (121856 + 1536)   // red[128]+red2[128]+mrow[64]+lrow[64] = 1536 B
__global__ void __launch_bounds__(256, 1) attn_tc_kernel(const float* __restrict__ q,
                                                         const float* __restrict__ kv,
                                                         bf16* __restrict__ ohi,
                                                         bf16* __restrict__ olo) {
    extern __shared__ char smb[];
    float* Vt   = (float*)(smb + A_VT);
    float* Ps   = (float*)(smb + A_PS);
    float* red  = (float*)(smb + A_RED);
    float* red2 = red + 128;
    float* mrow = red2 + 128;
    float* lrow = mrow + 64;
    uint32_t sbase = (uint32_t)__cvta_generic_to_shared(smb);

    const int qt = 15 - blockIdx.x;
    const int head = blockIdx.y, b = blockIdx.z;
    const int tid = threadIdx.x, lane = tid & 31, wid = tid >> 5;
    const int g2 = lane >> 2, t4 = lane & 3;
    const int wm = (wid & 3) << 4;
    const int wn = wid >> 2;
    const int qbase = qt << 6;
    const size_t tok0 = (size_t)b * SEQ;
    const int hoff = head << 7;

#pragma unroll
    for (int it = 0; it < 8; it++) {
        int lin = tid + (it << 8);
        int r = lin >> 5, c4 = (lin & 31) << 2;
        float4 v = *(const float4*)(q + (tok0 + qbase + r) * 1024 + hoff + c4);
        float h0 = __bfloat162float(__float2bfloat16_rn(v.x));
        float h1 = __bfloat162float(__float2bfloat16_rn(v.y));
        float h2 = __bfloat162float(__float2bfloat16_rn(v.z));
        float h3 = __bfloat162float(__float2bfloat16_rn(v.w));
        *(uint2*)(smb + A_QHB + r*A_KB + c4*2) = make_uint2(packbf2(h0,h1), packbf2(h2,h3));
        *(uint2*)(smb + A_QLB + r*A_KB + c4*2) =
            make_uint2(packbf2(v.x-h0, v.y-h1), packbf2(v.z-h2, v.w-h3));
    }
    if (tid < 64) { mrow[tid] = -1e30f; lrow[tid] = 0.f; }

    float oacc[8][4];
#pragma unroll
    for (int j = 0; j < 8; j++)
#pragma unroll
        for (int c = 0; c < 4; c++) oacc[j][c] = 0.f;

    const int r0 = wm + g2, r1 = r0 + 8;

    for (int kt = 0; kt <= qt; kt++) {
        __syncthreads();
#pragma unroll
        for (int it = 0; it < 8; it++) {
            int lin = tid + (it << 8);
            int r = lin >> 5, c4 = (lin & 31) << 2;
            const float* krow = kv + (tok0 + (kt<<6) + r) * 2048 + hoff;
            float4 kvv = *(const float4*)(krow + c4);
            float4 vv  = *(const float4*)(krow + 1024 + c4);
            float h0 = __bfloat162float(__float2bfloat16_rn(kvv.x));
            float h1 = __bfloat162float(__float2bfloat16_rn(kvv.y));
            float h2 = __bfloat162float(__float2bfloat16_rn(kvv.z));
            float h3 = __bfloat162float(__float2bfloat16_rn(kvv.w));
            *(uint2*)(smb + A_KHB + r*A_KB + c4*2) = make_uint2(packbf2(h0,h1), packbf2(h2,h3));
            *(uint2*)(smb + A_KLB + r*A_KB + c4*2) =
                make_uint2(packbf2(kvv.x-h0, kvv.y-h1), packbf2(kvv.z-h2, kvv.w-h3));
            *(float4*)(Vt + r*A_LDV + c4) =
                make_float4(cvt_tf32(vv.x), cvt_tf32(vv.y), cvt_tf32(vv.z), cvt_tf32(vv.w));
        }
        __syncthreads();
        float sacc[4][4];
#pragma unroll
        for (int j = 0; j < 4; j++)
#pragma unroll
            for (int c = 0; c < 4; c++) sacc[j][c] = 0.f;
#pragma unroll
        for (int kk = 0; kk < 8; kk++) {
            uint32_t ka = kk * 32u;
            uint32_t arow = (uint32_t)((wm + (lane & 15)) * A_KB) + ((lane >> 4) * 16) + ka;
            uint32_t aqh[4], aql[4];
            ldsm4(aqh, sbase + A_QHB + arow);
            ldsm4(aql, sbase + A_QLB + arow);
            uint32_t bh[4][2], bl[4][2];
            {
                int g = lane >> 3;
                int kblk = g & 1, rblk = g >> 1;
                uint32_t brow = (uint32_t)(((wn<<5) + rblk*8 + (lane & 7)) * A_KB) + kblk*16 + ka;
#pragma unroll
                for (int jp = 0; jp < 2; jp++) {
                    uint32_t tmp[4];
                    ldsm4(tmp, sbase + A_KHB + brow + jp * (16*A_KB));
                    bh[2*jp][0]=tmp[0]; bh[2*jp][1]=tmp[1];
                    bh[2*jp+1][0]=tmp[2]; bh[2*jp+1][1]=tmp[3];
                    ldsm4(tmp, sbase + A_KLB + brow + jp * (16*A_KB));
                    bl[2*jp][0]=tmp[0]; bl[2*jp][1]=tmp[1];
                    bl[2*jp+1][0]=tmp[2]; bl[2*jp+1][1]=tmp[3];
                }
            }
#pragma unroll
            for (int j = 0; j < 4; j++) {
                mma16(sacc[j], aqh, bh[j]);
                mma16(sacc[j], aqh, bl[j]);
                mma16(sacc[j], aql, bh[j]);
            }
        }
#pragma unroll
        for (int j = 0; j < 4; j++)
#pragma unroll
            for (int c = 0; c < 4; c++) sacc[j][c] *= SCALE_F;
        if (kt == qt) {
            int grow0 = qbase + r0, grow1 = qbase + r1;
#pragma unroll
            for (int j = 0; j < 4; j++) {
                int col = (kt<<6) + (wn<<5) + (j<<3) + (t4<<1);
                if (col   > grow0) sacc[j][0] = -1e30f;
                if (col+1 > grow0) sacc[j][1] = -1e30f;
                if (col   > grow1) sacc[j][2] = -1e30f;
                if (col+1 > grow1) sacc[j][3] = -1e30f;
            }
        }
        float mx0 = fmaxf(fmaxf(sacc[0][0], sacc[0][1]), fmaxf(sacc[1][0], sacc[1][1]));
        mx0 = fmaxf(mx0, fmaxf(fmaxf(sacc[2][0], sacc[2][1]), fmaxf(sacc[3][0], sacc[3][1])));
        float mx1 = fmaxf(fmaxf(sacc[0][2], sacc[0][3]), fmaxf(sacc[1][2], sacc[1][3]));
        mx1 = fmaxf(mx1, fmaxf(fmaxf(sacc[2][2], sacc[2][3]), fmaxf(sacc[3][2], sacc[3][3])));
        mx0 = fmaxf(mx0, __shfl_xor_sync(0xffffffffu, mx0, 1));
        mx0 = fmaxf(mx0, __shfl_xor_sync(0xffffffffu, mx0, 2));
        mx1 = fmaxf(mx1, __shfl_xor_sync(0xffffffffu, mx1, 1));
        mx1 = fmaxf(mx1, __shfl_xor_sync(0xffffffffu, mx1, 2));
        if (t4 == 0) { red[(r0<<1) + wn] = mx0; red[(r1<<1) + wn] = mx1; }
        __syncthreads();
        float mo0 = mrow[r0], mo1 = mrow[r1];
        float mn0 = fmaxf(mo0, fmaxf(red[r0<<1], red[(r0<<1)+1]));
        float mn1 = fmaxf(mo1, fmaxf(red[r1<<1], red[(r1<<1)+1]));
        float f0 = __expf(mo0 - mn0), f1 = __expf(mo1 - mn1);
        float ps0 = 0.f, ps1 = 0.f;
#pragma unroll
        for (int j = 0; j < 4; j++) {
            float p0 = __expf(sacc[j][0] - mn0), p1 = __expf(sacc[j][1] - mn0);
            float p2 = __expf(sacc[j][2] - mn1), p3 = __expf(sacc[j][3] - mn1);
            ps0 += p0 + p1; ps1 += p2 + p3;
            int pc = (wn<<5) + (j<<3) + (t4<<1);
            *(float2*)(Ps + r0*A_LDP + pc) = make_float2(cvt_tf32(p0), cvt_tf32(p1));
            *(float2*)(Ps + r1*A_LDP + pc) = make_float2(cvt_tf32(p2), cvt_tf32(p3));
        }
        ps0 += __shfl_xor_sync(0xffffffffu, ps0, 1);
        ps0 += __shfl_xor_sync(0xffffffffu, ps0, 2);
        ps1 += __shfl_xor_sync(0xffffffffu, ps1, 1);
        ps1 += __shfl_xor_sync(0xffffffffu, ps1, 2);
        if (t4 == 0) { red2[(r0<<1) + wn] = ps0; red2[(r1<<1) + wn] = ps1; }
#pragma unroll
        for (int j = 0; j < 8; j++) {
            oacc[j][0] *= f0; oacc[j][1] *= f0;
            oacc[j][2] *= f1; oacc[j][3] *= f1;
        }
        __syncthreads();
        if (wn == 0 && t4 == 0) {
            mrow[r0] = mn0; lrow[r0] = lrow[r0] * f0 + red2[r0<<1] + red2[(r0<<1)+1];
            mrow[r1] = mn1; lrow[r1] = lrow[r1] * f1 + red2[r1<<1] + red2[(r1<<1)+1];
        }
#pragma unroll
        for (int kk = 0; kk < 8; kk++) {
            int kc = (kk << 3) + t4;
            float a0 = Ps[r0*A_LDP + kc], a1 = Ps[r1*A_LDP + kc];
            float a2 = Ps[r0*A_LDP + kc + 4], a3 = Ps[r1*A_LDP + kc + 4];
#pragma unroll
            for (int j = 0; j < 8; j++) {
                int bc = (wn<<6) + (j<<3) + g2;
                float b0 = Vt[kc*A_LDV + bc];
                float b1 = Vt[(kc+4)*A_LDV + bc];
                mma8(oacc[j], a0, a1, a2, a3, b0, b1);
            }
        }
    }
    __syncthreads();
    float il0 = 1.f / lrow[r0], il1 = 1.f / lrow[r1];
#pragma unroll
    for (int j = 0; j < 8; j++) {
        int col = hoff + (wn<<6) + (j<<3) + (t4<<1);
        size_t o0 = (tok0 + qbase + r0) * 1024 + col;
        size_t o1 = (tok0 + qbase + r1) * 1024 + col;
        float v00 = oacc[j][0]*il0, v01 = oacc[j][1]*il0;
        float v10 = oacc[j][2]*il1, v11 = oacc[j][3]*il1;
        float h00 = __bfloat162float(__float2bfloat16_rn(v00));
        float h01 = __bfloat162float(__float2bfloat16_rn(v01));
        float h10 = __bfloat162float(__float2bfloat16_rn(v10));
        float h11 = __bfloat162float(__float2bfloat16_rn(v11));
        *(uint32_t*)(ohi + o0) = packbf2(h00, h01);
        *(uint32_t*)(ohi + o1) = packbf2(h10, h11);
        *(uint32_t*)(olo + o0) = packbf2(v00-h00, v01-h01);
        *(uint32_t*)(olo + o1) = packbf2(v10-h10, v11-h11);
    }
}

// ---------------- MoE gate ---------------
__global__ void gate_kernel(const float* __restrict__ h2, const float* __restrict__ gw) {
    int t = blockIdx.x;
    int w = threadIdx.x >> 5, lane = threadIdx.x & 31;
    const float* xr = h2 + (size_t)t * HD;
    const float* gr = gw + (size_t)w * HD;
    float ss = 0.f;
    for (int i = lane; i < HD; i += 32) ss += xr[i] * gr[i];
#pragma unroll
    for (int o = 16; o > 0; o >>= 1) ss += __shfl_down_sync(0xffffffffu, ss, o);
    __shared__ float lg[NEXP];
    if (lane == 0) lg[w] = ss;
    __syncthreads();
    if (threadIdx.x == 0) {
        int i1 = 0;
#pragma unroll
        for (int e = 1; e < NEXP; e++) if (lg[e] > lg[i1]) i1 = e;
        int i2 = (i1 == 0) ? 1 : 0;
#pragma unroll
        for (int e = 0; e < NEXP; e++) if (e != i1 && lg[e] > lg[i2]) i2 = e;
        float e2 = expf(lg[i2] - lg[i1]);
        float inv = 1.f / (1.f + e2);
        g_topi[2*t]   = i1; g_topw[2*t]   = inv;
        g_topi[2*t+1] = i2; g_topw[2*t+1] = e2 * inv;
    }
}

// ---------------- deterministic expert grouping --------------------------
__global__ void route_group_kernel() {
    __shared__ int hist[NEXP * 256];
    __shared__ int soff[NEXP + 1];
    __shared__ int stot[NEXP];
    int tid = threadIdx.x;
    int t0 = tid * 8;
    int lc[NEXP];
#pragma unroll
    for (int e = 0; e < NEXP; e++) lc[e] = 0;
    for (int t = t0; t < t0 + 8; t++) {
        lc[g_topi[2*t]]++; lc[g_topi[2*t+1]]++;
    }
#pragma unroll
    for (int e = 0; e < NEXP; e++) hist[e * 256 + tid] = lc[e];
    __syncthreads();
    if (tid < NEXP) {
        int a = 0;
        for (int i = 0; i < 256; i++) { int v = hist[tid*256+i]; hist[tid*256+i] = a; a += v; }
        stot[tid] = a;
    }
    __syncthreads();
    if (tid == 0) {
        int a = 0;
        for (int e = 0; e < NEXP; e++) { soff[e] = a; g_off[e] = a; g_cnt[e] = stot[e]; a += stot[e]; }
        soff[NEXP] = a;
    }
    __syncthreads();
    int pos[NEXP];
#pragma unroll
    for (int e = 0; e < NEXP; e++) pos[e] = soff[e] + hist[e * 256 + tid];
    for (int t = t0; t < t0 + 8; t++) {
        for (int s2 = 0; s2 < 2; s2++) {
            int e = g_topi[2*t + s2];
            int p = pos[e]++;
            g_ptok[p] = t; g_pdst[p] = 2*t + s2; g_pscale[p] = g_topw[2*t + s2];
        }
    }
}

// ---------------- elementwise tails --------------------------------------
__global__ void swiglu_kernel(const float* __restrict__ gu, float* __restrict__ act) {
    int t = blockIdx.x, i = threadIdx.x;
    float4 g = *(const float4*)(gu + (size_t)t*2048 + 4*i);
    float4 u = *(const float4*)(gu + (size_t)t*2048 + 1024 + 4*i);
    float4 r;
    r.x = g.x / (1.f + expf(-g.x)) * u.x;
    r.y = g.y / (1.f + expf(-g.y)) * u.y;
    r.z = g.z / (1.f + expf(-g.z)) * u.z;
    r.w = g.w / (1.f + expf(-g.w)) * u.w;
    *(float4*)(act + (size_t)t*HD + 4*i) = r;
}

__global__ void add_routed_kernel(float* __restrict__ out) {
    int t = blockIdx.x, i = threadIdx.x;
    float4 a = *(const float4*)(out + (size_t)t*HD + 4*i);
    float4 y0 = *(const float4*)(g_ybuf + (size_t)(2*t)*HD + 4*i);
    float4 y1 = *(const float4*)(g_ybuf + (size_t)(2*t+1)*HD + 4*i);
    a.x += y0.x + y1.x; a.y += y0.y + y1.y; a.z += y0.z + y1.z; a.w += y0.w + y1.w;
    *(float4*)(out + (size_t)t*HD + 4*i) = a;
}

// ---------------- launch ---------------------------------------------------
extern "C" void kernel_launch(void* const* d_in, const int* in_sizes, int n_in,
                              void* d_out, int out_size) {
    const float* x    = (const float*)d_in[0];
    const float* ln1  = (const float*)d_in[2];
    const float* ln2  = (const float*)d_in[3];
    const float* Wq   = (const float*)d_in[4];
    const float* Wkv  = (const float*)d_in[5];
    const float* Wo   = (const float*)d_in[6];
    const float* gate = (const float*)d_in[7];
    const float* w1   = (const float*)d_in[8];
    const float* w2   = (const float*)d_in[9];
    const float* sgu  = (const float*)d_in[10];
    const float* sdwn = (const float*)d_in[11];
    float* out = (float*)d_out;

    bf16 *p_wq_hi,*p_wq_lo,*p_wkv_hi,*p_wkv_lo,*p_wo_hi,*p_wo_lo;
    bf16 *p_h_hi,*p_h_lo,*p_o_hi,*p_o_lo;
    float *p_q,*p_kv,*p_x2,*p_h2,*p_gu,*p_act,*p_he;
    cudaGetSymbolAddress((void**)&p_wq_hi,  g_wq_hi);
    cudaGetSymbolAddress((void**)&p_wq_lo,  g_wq_lo);
    cudaGetSymbolAddress((void**)&p_wkv_hi, g_wkv_hi);
    cudaGetSymbolAddress((void**)&p_wkv_lo, g_wkv_lo);
    cudaGetSymbolAddress((void**)&p_wo_hi,  g_wo_hi);
    cudaGetSymbolAddress((void**)&p_wo_lo,  g_wo_lo);
    cudaGetSymbolAddress((void**)&p_h_hi,   g_h_hi);
    cudaGetSymbolAddress((void**)&p_h_lo,   g_h_lo);
    cudaGetSymbolAddress((void**)&p_o_hi,   g_o_hi);
    cudaGetSymbolAddress((void**)&p_o_lo,   g_o_lo);
    cudaGetSymbolAddress((void**)&p_q,      g_q);
    cudaGetSymbolAddress((void**)&p_kv,     g_kv);
    cudaGetSymbolAddress((void**)&p_x2,     g_x2);
    cudaGetSymbolAddress((void**)&p_h2,     g_h2);
    cudaGetSymbolAddress((void**)&p_gu,     g_gu);
    cudaGetSymbolAddress((void**)&p_act,    g_act);
    cudaGetSymbolAddress((void**)&p_he,     g_he);

    cudaFuncSetAttribute(attn_tc_kernel, cudaFuncAttributeMaxDynamicSharedMemorySize, ATTN3_BYTES);
    const int SM_P1 = 3 * 2 * MATS * 4;   // 110592 B (3-stage tf32)
    const int SM_BF = 2 * STAGEB;         // 81920 B (2-stage bf16)
    cudaFuncSetAttribute(gemm_bf3<0>, cudaFuncAttributeMaxDynamicSharedMemorySize, SM_BF);
    cudaFuncSetAttribute(gemm_bf3<1>, cudaFuncAttributeMaxDynamicSharedMemorySize, SM_BF);
    cudaFuncSetAttribute(gemm_cp<0>, cudaFuncAttributeMaxDynamicSharedMemorySize, SM_P1);
    cudaFuncSetAttribute(gemm_cp<1>, cudaFuncAttributeMaxDynamicSharedMemorySize, SM_P1);
    cudaFuncSetAttribute(gemm_cp<2>, cudaFuncAttributeMaxDynamicSharedMemorySize, SM_P1);
    cudaFuncSetAttribute(gemm_cp<3>, cudaFuncAttributeMaxDynamicSharedMemorySize, SM_P1);

    // weight bf16 hi/lo splits for routing-critical GEMMs
    pack_wq_kernel<<<1024, 256>>>(Wq, p_wq_hi, p_wq_lo);
    split_kernel<<<2048, 256>>>(Wkv, p_wkv_hi, p_wkv_lo);
    split_kernel<<<1024, 256>>>(Wo, p_wo_hi, p_wo_lo);

    // attention block
    rmsnorm_kernel<1><<<TT, 256>>>(x, ln1, p_h_hi, p_h_lo);
    gemm_bf3<0><<<dim3(8, 16), 256, SM_BF>>>(p_h_hi, p_h_lo, p_wq_hi, p_wq_lo,
                                             p_q, nullptr, 1024, 1024, 1024, 1024);
    gemm_bf3<0><<<dim3(16,16), 256, SM_BF>>>(p_h_hi, p_h_lo, p_wkv_hi, p_wkv_lo,
                                             p_kv, nullptr, 1024, 1024, 1024, 2048);
    attn_tc_kernel<<<dim3(16, NH, 2), 256, ATTN3_BYTES>>>(p_q, p_kv, p_o_hi, p_o_lo);
    gemm_bf3<1><<<dim3(8, 16), 256, SM_BF>>>(p_o_hi, p_o_lo, p_wo_hi, p_wo_lo,
                                             p_x2, x, 1024, 1024, 1024, 1024);

    // MoE block
    rmsnorm_kernel<0><<<TT, 256>>>(p_x2, ln2, p_h2, nullptr);
    gate_kernel<<<TT, 256>>>(p_h2, gate);
    route_group_kernel<<<1, 256>>>();
    gemm_cp<2><<<dim3(8, 32, NEXP), 256, SM_P1>>>(p_h2, w1, nullptr, nullptr,
                                                  1024, 1024, 1024, 1024);
    gemm_cp<3><<<dim3(8, 32, NEXP), 256, SM_P1>>>(p_he, w2, nullptr, nullptr,
                                                  1024, 1024, 1024, 1024);

    // shared expert
    gemm_cp<0><<<dim3(16,16), 256, SM_P1>>>(p_h2, sgu, p_gu, nullptr,
                                            1024, 1024, 1024, 2048);
    swiglu_kernel<<<TT, 256>>>(p_gu, p_act);
    gemm_cp<1><<<dim3(8, 16), 256, SM_P1>>>(p_act, sdwn, out, p_x2,
                                            1024, 1024, 1024, 1024);

    // combine routed experts
    add_routed_kernel<<<TT, 256>>>(out);
}

// round 12
// speedup vs baseline: 1.5543x; 1.1527x over previous
#include <cuda_runtime.h>
#include <cuda_bf16.h>
#include <cuda_fp16.h>
#include <stdint.h>
#include <math.h>

#define TT    2048
#define HD    1024
#define NH    8
#define SEQ   1024
#define NEXP  8
#define SCALE_F 0.07216878364870322f   // 192^-0.5

typedef __nv_bfloat16 bf16;

// ---------------- scratch ----------------
__device__ bf16  g_wq_hi [1024*1024];
__device__ bf16  g_wq_lo [1024*1024];
__device__ bf16  g_wkv_hi[2048*1024];
__device__ bf16  g_wkv_lo[2048*1024];
__device__ bf16  g_wo_hi [1024*1024];
__device__ bf16  g_wo_lo [1024*1024];
__device__ bf16  g_h_hi  [TT*HD];
__device__ bf16  g_h_lo  [TT*HD];
__device__ bf16  g_o_hi  [TT*1024];
__device__ bf16  g_o_lo  [TT*1024];
__device__ __half g_w1h  [8*1024*1024];
__device__ __half g_w2h  [8*1024*1024];
__device__ __half g_sguh [2048*1024];
__device__ __half g_sdwnh[1024*1024];
__device__ __half g_h2h  [TT*HD];
__device__ __half g_acth [TT*1024];
__device__ __half g_heh  [2*TT*1024];
__device__ float g_q     [TT*1024];
__device__ float g_kv    [TT*2048];
__device__ float g_x2    [TT*HD];
__device__ float g_h2    [TT*HD];
__device__ float g_gu    [TT*2048];
__device__ float g_ybuf  [2*TT*1024];
__device__ float g_topw  [2*TT];
__device__ float g_pscale[2*TT];
__device__ int   g_topi[2*TT];
__device__ int   g_ptok[2*TT];
__device__ int   g_pdst[2*TT];
__device__ int   g_cnt [NEXP];
__device__ int   g_off [NEXP];

// ---------------- helpers ----------------
__device__ __forceinline__ float cvt_tf32(float x) {
    unsigned u; asm("cvt.rna.tf32.f32 %0, %1;" : "=r"(u) : "f"(x));
    return __uint_as_float(u);
}
__device__ __forceinline__ void mma8(float* d, float a0, float a1, float a2, float a3,
                                     float b0, float b1) {
    unsigned A0=__float_as_uint(a0), A1=__float_as_uint(a1);
    unsigned A2=__float_as_uint(a2), A3=__float_as_uint(a3);
    unsigned B0=__float_as_uint(b0), B1=__float_as_uint(b1);
    asm volatile("mma.sync.aligned.m16n8k8.row.col.f32.tf32.tf32.f32 "
                 "{%0,%1,%2,%3},{%4,%5,%6,%7},{%8,%9},{%0,%1,%2,%3};"
                 : "+f"(d[0]), "+f"(d[1]), "+f"(d[2]), "+f"(d[3])
                 : "r"(A0), "r"(A1), "r"(A2), "r"(A3), "r"(B0), "r"(B1));
}
__device__ __forceinline__ void mma16(float* d, const uint32_t* a, const uint32_t* b) {
    asm volatile("mma.sync.aligned.m16n8k16.row.col.f32.bf16.bf16.f32 "
                 "{%0,%1,%2,%3},{%4,%5,%6,%7},{%8,%9},{%0,%1,%2,%3};"
                 : "+f"(d[0]), "+f"(d[1]), "+f"(d[2]), "+f"(d[3])
                 : "r"(a[0]), "r"(a[1]), "r"(a[2]), "r"(a[3]), "r"(b[0]), "r"(b[1]));
}
__device__ __forceinline__ void mma16h(float* d, const uint32_t* a, const uint32_t* b) {
    asm volatile("mma.sync.aligned.m16n8k16.row.col.f32.f16.f16.f32 "
                 "{%0,%1,%2,%3},{%4,%5,%6,%7},{%8,%9},{%0,%1,%2,%3};"
                 : "+f"(d[0]), "+f"(d[1]), "+f"(d[2]), "+f"(d[3])
                 : "r"(a[0]), "r"(a[1]), "r"(a[2]), "r"(a[3]), "r"(b[0]), "r"(b[1]));
}
__device__ __forceinline__ void ldsm4(uint32_t* r, uint32_t a) {
    asm volatile("ldmatrix.sync.aligned.m8n8.x4.shared.b16 {%0,%1,%2,%3}, [%4];"
                 : "=r"(r[0]), "=r"(r[1]), "=r"(r[2]), "=r"(r[3]) : "r"(a));
}
__device__ __forceinline__ void cp16(uint32_t s, const void* g) {
    asm volatile("cp.async.cg.shared.global [%0], [%1], 16;" :: "r"(s), "l"(g));
}
__device__ __forceinline__ void cpcommit() { asm volatile("cp.async.commit_group;"); }
template<int N> __device__ __forceinline__ void cpwait() {
    asm volatile("cp.async.wait_group %0;" :: "n"(N));
}
__device__ __forceinline__ uint32_t packbf2(float a, float b) {
    __nv_bfloat162 t = __floats2bfloat162_rn(a, b);
    return *(uint32_t*)&t;
}
__device__ __forceinline__ uint32_t packh2(float a, float b) {
    __half2 t = __floats2half2_rn(a, b);
    return *(uint32_t*)&t;
}

// ---------------- pack Wq (nope rows only) + bf16 hi/lo split -------------
__global__ void pack_wq_kernel(const float* __restrict__ Wq,
                               bf16* __restrict__ hi, bf16* __restrict__ lo) {
    int r = blockIdx.x;
    int h = r >> 7, d = r & 127;
    float4 v = ((const float4*)(Wq + (size_t)(h*192 + d) * HD))[threadIdx.x];
    float h0 = __bfloat162float(__float2bfloat16_rn(v.x));
    float h1 = __bfloat162float(__float2bfloat16_rn(v.y));
    float h2 = __bfloat162float(__float2bfloat16_rn(v.z));
    float h3 = __bfloat162float(__float2bfloat16_rn(v.w));
    ((uint2*)(hi + (size_t)r * HD))[threadIdx.x] = make_uint2(packbf2(h0,h1), packbf2(h2,h3));
    ((uint2*)(lo + (size_t)r * HD))[threadIdx.x] =
        make_uint2(packbf2(v.x-h0, v.y-h1), packbf2(v.z-h2, v.w-h3));
}

// ---------------- generic bf16 hi/lo split --------------------------------
__global__ void split_kernel(const float* __restrict__ src,
                             bf16* __restrict__ hi, bf16* __restrict__ lo) {
    size_t i = ((size_t)blockIdx.x * 256 + threadIdx.x);
    float4 v = ((const float4*)src)[i];
    float h0 = __bfloat162float(__float2bfloat16_rn(v.x));
    float h1 = __bfloat162float(__float2bfloat16_rn(v.y));
    float h2 = __bfloat162float(__float2bfloat16_rn(v.z));
    float h3 = __bfloat162float(__float2bfloat16_rn(v.w));
    ((uint2*)hi)[i] = make_uint2(packbf2(h0, h1), packbf2(h2, h3));
    ((uint2*)lo)[i] = make_uint2(packbf2(v.x-h0, v.y-h1), packbf2(v.z-h2, v.w-h3));
}

// ---------------- generic fp32 -> fp16 convert ----------------------------
__global__ void cvt_h_kernel(const float* __restrict__ src, __half* __restrict__ dst) {
    size_t i = ((size_t)blockIdx.x * 256 + threadIdx.x);
    float4 v = ((const float4*)src)[i];
    ((uint2*)dst)[i] = make_uint2(packh2(v.x, v.y), packh2(v.z, v.w));
}

// ---------------- rmsnorm (SPLIT=1: bf16 hi/lo; 0: fp32) ------------------
template<int SPLIT>
__global__ void rmsnorm_kernel(const float* __restrict__ x, const float* __restrict__ w,
                               void* __restrict__ out, bf16* __restrict__ out_lo) {
    int t = blockIdx.x;
    float4 v = ((const float4*)(x + (size_t)t * HD))[threadIdx.x];
    float ss = v.x*v.x + v.y*v.y + v.z*v.z + v.w*v.w;
    __shared__ float red[256];
    red[threadIdx.x] = ss; __syncthreads();
    for (int o = 128; o > 0; o >>= 1) {
        if (threadIdx.x < o) red[threadIdx.x] += red[threadIdx.x + o];
        __syncthreads();
    }
    float inv = rsqrtf(red[0] * (1.f / HD) + 1e-6f);
    float4 wv = ((const float4*)w)[threadIdx.x];
    float o0 = v.x*inv*wv.x, o1 = v.y*inv*wv.y, o2 = v.z*inv*wv.z, o3 = v.w*inv*wv.w;
    if (SPLIT) {
        float h0 = __bfloat162float(__float2bfloat16_rn(o0));
        float h1 = __bfloat162float(__float2bfloat16_rn(o1));
        float h2 = __bfloat162float(__float2bfloat16_rn(o2));
        float h3 = __bfloat162float(__float2bfloat16_rn(o3));
        ((uint2*)((bf16*)out + (size_t)t * HD))[threadIdx.x] =
            make_uint2(packbf2(h0, h1), packbf2(h2, h3));
        ((uint2*)(out_lo + (size_t)t * HD))[threadIdx.x] =
            make_uint2(packbf2(o0-h0, o1-h1), packbf2(o2-h2, o3-h3));
    } else {
        ((float4*)((float*)out + (size_t)t * HD))[threadIdx.x] = make_float4(o0, o1, o2, o3);
    }
}

// ---------------- bf16 3-pass GEMM (NT), ldmatrix + cp.async --------------
// C = Ahi*Bhi + Ahi*Blo + Alo*Bhi   (routing-critical path)
#define MATB 10240          // bytes per 128x32 bf16 matrix with 80B row stride
#define STAGEB (4*MATB)     // 40960 B per stage
template<int MODE>
__global__ void __launch_bounds__(256, 2)
gemm_bf3(const bf16* __restrict__ Ah_, const bf16* __restrict__ Al_,
         const bf16* __restrict__ Bh_, const bf16* __restrict__ Bl_,
         float* __restrict__ C, const float* __restrict__ R,
         int K, int lda, int ldb, int ldc) {
    extern __shared__ char smc[];
    const int bm = blockIdx.y << 7, bn = blockIdx.x << 7;
    const int tid = threadIdx.x;
    const int lane = tid & 31, w = tid >> 5;
    const int g2 = lane >> 2, t4 = lane & 3;
    const int wm = (w >> 2) << 6, wn = (w & 3) << 5;
    const int rb = tid >> 2, seg = tid & 3;
    uint32_t sbase = (uint32_t)__cvta_generic_to_shared(smc);

    auto fill = [&](int st, int k0) {
        uint32_t s0 = sbase + (uint32_t)st * STAGEB;
        const bf16* gA_h = Ah_ + (size_t)(bm + rb) * lda + k0 + seg*8;
        const bf16* gA_l = Al_ + (size_t)(bm + rb) * lda + k0 + seg*8;
        const bf16* gB_h = Bh_ + (size_t)(bn + rb) * ldb + k0 + seg*8;
        const bf16* gB_l = Bl_ + (size_t)(bn + rb) * ldb + k0 + seg*8;
        uint32_t so = (uint32_t)(rb * 80 + seg * 16);
        uint32_t so2 = so + 64u * 80u;
        size_t stride64A = (size_t)64 * lda, stride64B = (size_t)64 * ldb;
        cp16(s0 + so,              gA_h);
        cp16(s0 + so2,             gA_h + stride64A);
        cp16(s0 + MATB + so,       gA_l);
        cp16(s0 + MATB + so2,      gA_l + stride64A);
        cp16(s0 + 2*MATB + so,     gB_h);
        cp16(s0 + 2*MATB + so2,    gB_h + stride64B);
        cp16(s0 + 3*MATB + so,     gB_l);
        cp16(s0 + 3*MATB + so2,    gB_l + stride64B);
        cpcommit();
    };

    float acc[4][4][4];
#pragma unroll
    for (int i = 0; i < 4; i++)
#pragma unroll
        for (int j = 0; j < 4; j++)
#pragma unroll
            for (int q = 0; q < 4; q++) acc[i][j][q] = 0.f;

    auto compute = [&](int st) {
        uint32_t sb = sbase + (uint32_t)st * STAGEB;
#pragma unroll
        for (int kk = 0; kk < 2; kk++) {
            uint32_t ka = kk * 32u;
            uint32_t arow = (uint32_t)((wm + (lane & 15)) * 80) + ((lane >> 4) * 16) + ka;
            uint32_t ahh[4][4], ahl[4][4];
#pragma unroll
            for (int i = 0; i < 4; i++) {
                ldsm4(ahh[i], sb + arow + i * (16*80));
                ldsm4(ahl[i], sb + MATB + arow + i * (16*80));
            }
            uint32_t bhh[4][2], bhl[4][2];
            {
                int g = lane >> 3;
                int kblk = g & 1, rblk = g >> 1;
                uint32_t brow = (uint32_t)((wn + rblk*8 + (lane & 7)) * 80) + kblk*16 + ka;
#pragma unroll
                for (int jp = 0; jp < 2; jp++) {
                    uint32_t tmp[4];
                    ldsm4(tmp, sb + 2*MATB + brow + jp * (16*80));
                    bhh[2*jp][0]=tmp[0]; bhh[2*jp][1]=tmp[1];
                    bhh[2*jp+1][0]=tmp[2]; bhh[2*jp+1][1]=tmp[3];
                    ldsm4(tmp, sb + 3*MATB + brow + jp * (16*80));
                    bhl[2*jp][0]=tmp[0]; bhl[2*jp][1]=tmp[1];
                    bhl[2*jp+1][0]=tmp[2]; bhl[2*jp+1][1]=tmp[3];
                }
            }
#pragma unroll
            for (int i = 0; i < 4; i++)
#pragma unroll
                for (int j = 0; j < 4; j++) {
                    mma16(acc[i][j], ahh[i], bhh[j]);
                    mma16(acc[i][j], ahh[i], bhl[j]);
                    mma16(acc[i][j], ahl[i], bhh[j]);
                }
        }
    };

    const int NS = K >> 5;
    fill(0, 0);
    for (int ks = 0; ks < NS; ks++) {
        cpwait<0>();
        __syncthreads();
        if (ks + 1 < NS) fill((ks + 1) & 1, (ks + 1) << 5);
        compute(ks & 1);
    }

#pragma unroll
    for (int i = 0; i < 4; i++) {
#pragma unroll
        for (int j = 0; j < 4; j++) {
            int m0 = bm + wm + 16*i + g2, m1 = m0 + 8;
            int nc = bn + wn + 8*j + 2*t4;
            float2 v0 = make_float2(acc[i][j][0], acc[i][j][1]);
            float2 v1 = make_float2(acc[i][j][2], acc[i][j][3]);
            size_t o0 = (size_t)m0 * ldc + nc, o1 = (size_t)m1 * ldc + nc;
            if (MODE == 1) {
                float2 r0 = *(const float2*)(R + o0);
                float2 r1 = *(const float2*)(R + o1);
                v0.x += r0.x; v0.y += r0.y; v1.x += r1.x; v1.y += r1.y;
            }
            *(float2*)(C + o0) = v0;
            *(float2*)(C + o1) = v1;
        }
    }
}

// ---------------- fp16 1-pass GEMM (NT), ldmatrix + cp.async --------------
// Non-routing-critical paths (experts + shared). RN rounding, fp32 accum.
// MODE: 0 plain, 1 +residual, 2 expert1 (gather + SiLU -> g_heh fp16),
//       3 expert2 (A = g_heh rows, scaled scatter -> g_ybuf)
#define MATH_B 10240
#define HSTAGE (2*MATH_B)   // 20480 B per stage
template<int MODE>
__global__ void __launch_bounds__(256, 2)
gemm_hf(const __half* __restrict__ Ah_, const __half* __restrict__ Bh_,
        float* __restrict__ C, const float* __restrict__ R,
        int K, int lda, int ldb, int ldc) {
    extern __shared__ char smc[];
    const int NSTAGE = 3;
    const int bm = blockIdx.y << 7, bn = blockIdx.x << 7;
    int off = 0, cnt = 0x7fffffff;
    const __half* Bh = Bh_;
    if (MODE >= 2) {
        int e = blockIdx.z;
        cnt = g_cnt[e];
        if (cnt == 0 || bm >= cnt) return;
        off = g_off[e];
        Bh = Bh_ + (size_t)e * 1024 * 1024;
    }
    __shared__ int rowA[128];
    const int tid = threadIdx.x;
    if (MODE >= 2) {
        if (tid < 128) {
            int gr = bm + tid; if (gr >= cnt) gr = cnt - 1;
            rowA[tid] = (MODE == 2) ? g_ptok[off + gr] : (off + gr);
        }
        __syncthreads();
    }
    const int lane = tid & 31, w = tid >> 5;
    const int g2 = lane >> 2, t4 = lane & 3;
    const int wm = (w >> 2) << 6, wn = (w & 3) << 5;
    const int rb = tid >> 2, seg = tid & 3;
    uint32_t sbase = (uint32_t)__cvta_generic_to_shared(smc);

    auto fill = [&](int st, int k0) {
        uint32_t s0 = sbase + (uint32_t)st * HSTAGE;
        uint32_t so = (uint32_t)(rb * 80 + seg * 16);
        uint32_t so2 = so + 64u * 80u;
        const __half *a0, *a1;
        if (MODE >= 2) {
            a0 = Ah_ + (size_t)rowA[rb] * lda + k0 + seg*8;
            a1 = Ah_ + (size_t)rowA[rb + 64] * lda + k0 + seg*8;
        } else {
            a0 = Ah_ + (size_t)(bm + rb) * lda + k0 + seg*8;
            a1 = a0 + (size_t)64 * lda;
        }
        const __half* b0 = Bh + (size_t)(bn + rb) * ldb + k0 + seg*8;
        cp16(s0 + so,            a0);
        cp16(s0 + so2,           a1);
        cp16(s0 + MATH_B + so,   b0);
        cp16(s0 + MATH_B + so2,  b0 + (size_t)64 * ldb);
        cpcommit();
    };

    float acc[4][4][4];
#pragma unroll
    for (int i = 0; i < 4; i++)
#pragma unroll
        for (int j = 0; j < 4; j++)
#pragma unroll
            for (int q = 0; q < 4; q++) acc[i][j][q] = 0.f;

    auto compute = [&](int st) {
        uint32_t sb = sbase + (uint32_t)st * HSTAGE;
#pragma unroll
        for (int kk = 0; kk < 2; kk++) {
            uint32_t ka = kk * 32u;
            uint32_t arow = (uint32_t)((wm + (lane & 15)) * 80) + ((lane >> 4) * 16) + ka;
            uint32_t ah[4][4];
#pragma unroll
            for (int i = 0; i < 4; i++)
                ldsm4(ah[i], sb + arow + i * (16*80));
            uint32_t bh[4][2];
            {
                int g = lane >> 3;
                int kblk = g & 1, rblk = g >> 1;
                uint32_t brow = (uint32_t)((wn + rblk*8 + (lane & 7)) * 80) + kblk*16 + ka;
#pragma unroll
                for (int jp = 0; jp < 2; jp++) {
                    uint32_t tmp[4];
                    ldsm4(tmp, sb + MATH_B + brow + jp * (16*80));
                    bh[2*jp][0]=tmp[0]; bh[2*jp][1]=tmp[1];
                    bh[2*jp+1][0]=tmp[2]; bh[2*jp+1][1]=tmp[3];
                }
            }
#pragma unroll
            for (int i = 0; i < 4; i++)
#pragma unroll
                for (int j = 0; j < 4; j++)
                    mma16h(acc[i][j], ah[i], bh[j]);
        }
    };

    const int NS = K >> 5;
    fill(0, 0);
    if (NS > 1) fill(1, 32);
    for (int ks = 0; ks < NS; ks++) {
        cpwait<1>();
        __syncthreads();
        int nf = ks + NSTAGE - 1;
        if (nf < NS) fill(nf % NSTAGE, nf << 5);
        compute(ks % NSTAGE);
    }

#pragma unroll
    for (int i = 0; i < 4; i++) {
#pragma unroll
        for (int j = 0; j < 4; j++) {
            int m0 = bm + wm + 16*i + g2, m1 = m0 + 8;
            int nc = bn + wn + 8*j + 2*t4;
            float2 v0 = make_float2(acc[i][j][0], acc[i][j][1]);
            float2 v1 = make_float2(acc[i][j][2], acc[i][j][3]);
            if (MODE == 0 || MODE == 1) {
                size_t o0 = (size_t)m0 * ldc + nc, o1 = (size_t)m1 * ldc + nc;
                if (MODE == 1) {
                    float2 r0 = *(const float2*)(R + o0);
                    float2 r1 = *(const float2*)(R + o1);
                    v0.x += r0.x; v0.y += r0.y; v1.x += r1.x; v1.y += r1.y;
                }
                *(float2*)(C + o0) = v0;
                *(float2*)(C + o1) = v1;
            } else if (MODE == 2) {
                if (m0 < cnt) {
                    float s0v = v0.x/(1.f+expf(-v0.x)), s1v = v0.y/(1.f+expf(-v0.y));
                    *(uint32_t*)(g_heh + (size_t)(off+m0)*1024 + nc) = packh2(s0v, s1v);
                }
                if (m1 < cnt) {
                    float s0v = v1.x/(1.f+expf(-v1.x)), s1v = v1.y/(1.f+expf(-v1.y));
                    *(uint32_t*)(g_heh + (size_t)(off+m1)*1024 + nc) = packh2(s0v, s1v);
                }
            } else {
                if (m0 < cnt) {
                    int p = off + m0; float sc = g_pscale[p]; int d = g_pdst[p];
                    *(float2*)(g_ybuf + (size_t)d*1024 + nc) = make_float2(v0.x*sc, v0.y*sc);
                }
                if (m1 < cnt) {
                    int p = off + m1; float sc = g_pscale[p]; int d = g_pdst[p];
                    *(float2*)(g_ybuf + (size_t)d*1024 + nc) = make_float2(v1.x*sc, v1.y*sc);
                }
            }
        }
    }
}

// ---------------- flash attention: QK bf16 3-pass + PV tf32 ---------------
#define A_KB   272
#define A_QHB  0
#define A_QLB  17408
#define A_KHB  34816
#define A_KLB  52224
#define A_VT   69632
#define A_PS   104448
#define A_RED  121856
#define A_LDV 136
#define A_LDP 68
#define ATTN3_BYTES (121856 + 1536)
__global__ void __launch_bounds__(256, 1) attn_tc_kernel(const float* __restrict__ q,
                                                         const float* __restrict__ kv,
                                                         bf16* __restrict__ ohi,
                                                         bf16* __restrict__ olo) {
    extern __shared__ char smb[];
    float* Vt   = (float*)(smb + A_VT);
    float* Ps   = (float*)(smb + A_PS);
    float* red  = (float*)(smb + A_RED);
    float* red2 = red + 128;
    float* mrow = red2 + 128;
    float* lrow = mrow + 64;
    uint32_t sbase = (uint32_t)__cvta_generic_to_shared(smb);

    const int qt = 15 - blockIdx.x;
    const int head = blockIdx.y, b = blockIdx.z;
    const int tid = threadIdx.x, lane = tid & 31, wid = tid >> 5;
    const int g2 = lane >> 2, t4 = lane & 3;
    const int wm = (wid & 3) << 4;
    const int wn = wid >> 2;
    const int qbase = qt << 6;
    const size_t tok0 = (size_t)b * SEQ;
    const int hoff = head << 7;

#pragma unroll
    for (int it = 0; it < 8; it++) {
        int lin = tid + (it << 8);
        int r = lin >> 5, c4 = (lin & 31) << 2;
        float4 v = *(const float4*)(q + (tok0 + qbase + r) * 1024 + hoff + c4);
        float h0 = __bfloat162float(__float2bfloat16_rn(v.x));
        float h1 = __bfloat162float(__float2bfloat16_rn(v.y));
        float h2 = __bfloat162float(__float2bfloat16_rn(v.z));
        float h3 = __bfloat162float(__float2bfloat16_rn(v.w));
        *(uint2*)(smb + A_QHB + r*A_KB + c4*2) = make_uint2(packbf2(h0,h1), packbf2(h2,h3));
        *(uint2*)(smb + A_QLB + r*A_KB + c4*2) =
            make_uint2(packbf2(v.x-h0, v.y-h1), packbf2(v.z-h2, v.w-h3));
    }
    if (tid < 64) { mrow[tid] = -1e30f; lrow[tid] = 0.f; }

    float oacc[8][4];
#pragma unroll
    for (int j = 0; j < 8; j++)
#pragma unroll
        for (int c = 0; c < 4; c++) oacc[j][c] = 0.f;

    const int r0 = wm + g2, r1 = r0 + 8;

    for (int kt = 0; kt <= qt; kt++) {
        __syncthreads();
#pragma unroll
        for (int it = 0; it < 8; it++) {
            int lin = tid + (it << 8);
            int r = lin >> 5, c4 = (lin & 31) << 2;
            const float* krow = kv + (tok0 + (kt<<6) + r) * 2048 + hoff;
            float4 kvv = *(const float4*)(krow + c4);
            float4 vv  = *(const float4*)(krow + 1024 + c4);
            float h0 = __bfloat162float(__float2bfloat16_rn(kvv.x));
            float h1 = __bfloat162float(__float2bfloat16_rn(kvv.y));
            float h2 = __bfloat162float(__float2bfloat16_rn(kvv.z));
            float h3 = __bfloat162float(__float2bfloat16_rn(kvv.w));
            *(uint2*)(smb + A_KHB + r*A_KB + c4*2) = make_uint2(packbf2(h0,h1), packbf2(h2,h3));
            *(uint2*)(smb + A_KLB + r*A_KB + c4*2) =
                make_uint2(packbf2(kvv.x-h0, kvv.y-h1), packbf2(kvv.z-h2, kvv.w-h3));
            *(float4*)(Vt + r*A_LDV + c4) =
                make_float4(cvt_tf32(vv.x), cvt_tf32(vv.y), cvt_tf32(vv.z), cvt_tf32(vv.w));
        }
        __syncthreads();
        float sacc[4][4];
#pragma unroll
        for (int j = 0; j < 4; j++)
#pragma unroll
            for (int c = 0; c < 4; c++) sacc[j][c] = 0.f;
#pragma unroll
        for (int kk = 0; kk < 8; kk++) {
            uint32_t ka = kk * 32u;
            uint32_t arow = (uint32_t)((wm + (lane & 15)) * A_KB) + ((lane >> 4) * 16) + ka;
            uint32_t aqh[4], aql[4];
            ldsm4(aqh, sbase + A_QHB + arow);
            ldsm4(aql, sbase + A_QLB + arow);
            uint32_t bh[4][2], bl[4][2];
            {
                int g = lane >> 3;
                int kblk = g & 1, rblk = g >> 1;
                uint32_t brow = (uint32_t)(((wn<<5) + rblk*8 + (lane & 7)) * A_KB) + kblk*16 + ka;
#pragma unroll
                for (int jp = 0; jp < 2; jp++) {
                    uint32_t tmp[4];
                    ldsm4(tmp, sbase + A_KHB + brow + jp * (16*A_KB));
                    bh[2*jp][0]=tmp[0]; bh[2*jp][1]=tmp[1];
                    bh[2*jp+1][0]=tmp[2]; bh[2*jp+1][1]=tmp[3];
                    ldsm4(tmp, sbase + A_KLB + brow + jp * (16*A_KB));
                    bl[2*jp][0]=tmp[0]; bl[2*jp][1]=tmp[1];
                    bl[2*jp+1][0]=tmp[2]; bl[2*jp+1][1]=tmp[3];
                }
            }
#pragma unroll
            for (int j = 0; j < 4; j++) {
                mma16(sacc[j], aqh, bh[j]);
                mma16(sacc[j], aqh, bl[j]);
                mma16(sacc[j], aql, bh[j]);
            }
        }
#pragma unroll
        for (int j = 0; j < 4; j++)
#pragma unroll
            for (int c = 0; c < 4; c++) sacc[j][c] *= SCALE_F;
        if (kt == qt) {
            int grow0 = qbase + r0, grow1 = qbase + r1;
#pragma unroll
            for (int j = 0; j < 4; j++) {
                int col = (kt<<6) + (wn<<5) + (j<<3) + (t4<<1);
                if (col   > grow0) sacc[j][0] = -1e30f;
                if (col+1 > grow0) sacc[j][1] = -1e30f;
                if (col   > grow1) sacc[j][2] = -1e30f;
                if (col+1 > grow1) sacc[j][3] = -1e30f;
            }
        }
        float mx0 = fmaxf(fmaxf(sacc[0][0], sacc[0][1]), fmaxf(sacc[1][0], sacc[1][1]));
        mx0 = fmaxf(mx0, fmaxf(fmaxf(sacc[2][0], sacc[2][1]), fmaxf(sacc[3][0], sacc[3][1])));
        float mx1 = fmaxf(fmaxf(sacc[0][2], sacc[0][3]), fmaxf(sacc[1][2], sacc[1][3]));
        mx1 = fmaxf(mx1, fmaxf(fmaxf(sacc[2][2], sacc[2][3]), fmaxf(sacc[3][2], sacc[3][3])));
        mx0 = fmaxf(mx0, __shfl_xor_sync(0xffffffffu, mx0, 1));
        mx0 = fmaxf(mx0, __shfl_xor_sync(0xffffffffu, mx0, 2));
        mx1 = fmaxf(mx1, __shfl_xor_sync(0xffffffffu, mx1, 1));
        mx1 = fmaxf(mx1, __shfl_xor_sync(0xffffffffu, mx1, 2));
        if (t4 == 0) { red[(r0<<1) + wn] = mx0; red[(r1<<1) + wn] = mx1; }
        __syncthreads();
        float mo0 = mrow[r0], mo1 = mrow[r1];
        float mn0 = fmaxf(mo0, fmaxf(red[r0<<1], red[(r0<<1)+1]));
        float mn1 = fmaxf(mo1, fmaxf(red[r1<<1], red[(r1<<1)+1]));
        float f0 = __expf(mo0 - mn0), f1 = __expf(mo1 - mn1);
        float ps0 = 0.f, ps1 = 0.f;
#pragma unroll
        for (int j = 0; j < 4; j++) {
            float p0 = __expf(sacc[j][0] - mn0), p1 = __expf(sacc[j][1] - mn0);
            float p2 = __expf(sacc[j][2] - mn1), p3 = __expf(sacc[j][3] - mn1);
            ps0 += p0 + p1; ps1 += p2 + p3;
            int pc = (wn<<5) + (j<<3) + (t4<<1);
            *(float2*)(Ps + r0*A_LDP + pc) = make_float2(cvt_tf32(p0), cvt_tf32(p1));
            *(float2*)(Ps + r1*A_LDP + pc) = make_float2(cvt_tf32(p2), cvt_tf32(p3));
        }
        ps0 += __shfl_xor_sync(0xffffffffu, ps0, 1);
        ps0 += __shfl_xor_sync(0xffffffffu, ps0, 2);
        ps1 += __shfl_xor_sync(0xffffffffu, ps1, 1);
        ps1 += __shfl_xor_sync(0xffffffffu, ps1, 2);
        if (t4 == 0) { red2[(r0<<1) + wn] = ps0; red2[(r1<<1) + wn] = ps1; }
#pragma unroll
        for (int j = 0; j < 8; j++) {
            oacc[j][0] *= f0; oacc[j][1] *= f0;
            oacc[j][2] *= f1; oacc[j][3] *= f1;
        }
        __syncthreads();
        if (wn == 0 && t4 == 0) {
            mrow[r0] = mn0; lrow[r0] = lrow[r0] * f0 + red2[r0<<1] + red2[(r0<<1)+1];
            mrow[r1] = mn1; lrow[r1] = lrow[r1] * f1 + red2[r1<<1] + red2[(r1<<1)+1];
        }
#pragma unroll
        for (int kk = 0; kk < 8; kk++) {
            int kc = (kk << 3) + t4;
            float a0 = Ps[r0*A_LDP + kc], a1 = Ps[r1*A_LDP + kc];
            float a2 = Ps[r0*A_LDP + kc + 4], a3 = Ps[r1*A_LDP + kc + 4];
#pragma unroll
            for (int j = 0; j < 8; j++) {
                int bc = (wn<<6) + (j<<3) + g2;
                float b0 = Vt[kc*A_LDV + bc];
                float b1 = Vt[(kc+4)*A_LDV + bc];
                mma8(oacc[j], a0, a1, a2, a3, b0, b1);
            }
        }
    }
    __syncthreads();
    float il0 = 1.f / lrow[r0], il1 = 1.f / lrow[r1];
#pragma unroll
    for (int j = 0; j < 8; j++) {
        int col = hoff + (wn<<6) + (j<<3) + (t4<<1);
        size_t o0 = (tok0 + qbase + r0) * 1024 + col;
        size_t o1 = (tok0 + qbase + r1) * 1024 + col;
        float v00 = oacc[j][0]*il0, v01 = oacc[j][1]*il0;
        float v10 = oacc[j][2]*il1, v11 = oacc[j][3]*il1;
        float h00 = __bfloat162float(__float2bfloat16_rn(v00));
        float h01 = __bfloat162float(__float2bfloat16_rn(v01));
        float h10 = __bfloat162float(__float2bfloat16_rn(v10));
        float h11 = __bfloat162float(__float2bfloat16_rn(v11));
        *(uint32_t*)(ohi + o0) = packbf2(h00, h01);
        *(uint32_t*)(ohi + o1) = packbf2(h10, h11);
        *(uint32_t*)(olo + o0) = packbf2(v00-h00, v01-h01);
        *(uint32_t*)(olo + o1) = packbf2(v10-h10, v11-h11);
    }
}

// ---------------- MoE gate ---------------
__global__ void gate_kernel(const float* __restrict__ h2, const float* __restrict__ gw) {
    int t = blockIdx.x;
    int w = threadIdx.x >> 5, lane = threadIdx.x & 31;
    const float* xr = h2 + (size_t)t * HD;
    const float* gr = gw + (size_t)w * HD;
    float ss = 0.f;
    for (int i = lane; i < HD; i += 32) ss += xr[i] * gr[i];
#pragma unroll
    for (int o = 16; o > 0; o >>= 1) ss += __shfl_down_sync(0xffffffffu, ss, o);
    __shared__ float lg[NEXP];
    if (lane == 0) lg[w] = ss;
    __syncthreads();
    if (threadIdx.x == 0) {
        int i1 = 0;
#pragma unroll
        for (int e = 1; e < NEXP; e++) if (lg[e] > lg[i1]) i1 = e;
        int i2 = (i1 == 0) ? 1 : 0;
#pragma unroll
        for (int e = 0; e < NEXP; e++) if (e != i1 && lg[e] > lg[i2]) i2 = e;
        float e2 = expf(lg[i2] - lg[i1]);
        float inv = 1.f / (1.f + e2);
        g_topi[2*t]   = i1; g_topw[2*t]   = inv;
        g_topi[2*t+1] = i2; g_topw[2*t+1] = e2 * inv;
    }
}

// ---------------- deterministic expert grouping --------------------------
__global__ void route_group_kernel() {
    __shared__ int hist[NEXP * 256];
    __shared__ int soff[NEXP + 1];
    __shared__ int stot[NEXP];
    int tid = threadIdx.x;
    int t0 = tid * 8;
    int lc[NEXP];
#pragma unroll
    for (int e = 0; e < NEXP; e++) lc[e] = 0;
    for (int t = t0; t < t0 + 8; t++) {
        lc[g_topi[2*t]]++; lc[g_topi[2*t+1]]++;
    }
#pragma unroll
    for (int e = 0; e < NEXP; e++) hist[e * 256 + tid] = lc[e];
    __syncthreads();
    if (tid < NEXP) {
        int a = 0;
        for (int i = 0; i < 256; i++) { int v = hist[tid*256+i]; hist[tid*256+i] = a; a += v; }
        stot[tid] = a;
    }
    __syncthreads();
    if (tid == 0) {
        int a = 0;
        for (int e = 0; e < NEXP; e++) { soff[e] = a; g_off[e] = a; g_cnt[e] = stot[e]; a += stot[e]; }
        soff[NEXP] = a;
    }
    __syncthreads();
    int pos[NEXP];
#pragma unroll
    for (int e = 0; e < NEXP; e++) pos[e] = soff[e] + hist[e * 256 + tid];
    for (int t = t0; t < t0 + 8; t++) {
        for (int s2 = 0; s2 < 2; s2++) {
            int e = g_topi[2*t + s2];
            int p = pos[e]++;
            g_ptok[p] = t; g_pdst[p] = 2*t + s2; g_pscale[p] = g_topw[2*t + s2];
        }
    }
}

// ---------------- elementwise tails --------------------------------------
__global__ void swiglu_kernel(const float* __restrict__ gu, __half* __restrict__ act) {
    int t = blockIdx.x, i = threadIdx.x;
    float4 g = *(const float4*)(gu + (size_t)t*2048 + 4*i);
    float4 u = *(const float4*)(gu + (size_t)t*2048 + 1024 + 4*i);
    float r0 = g.x / (1.f + expf(-g.x)) * u.x;
    float r1 = g.y / (1.f + expf(-g.y)) * u.y;
    float r2 = g.z / (1.f + expf(-g.z)) * u.z;
    float r3 = g.w / (1.f + expf(-g.w)) * u.w;
    ((uint2*)(act + (size_t)t*1024))[i] = make_uint2(packh2(r0, r1), packh2(r2, r3));
}

__global__ void add_routed_kernel(float* __restrict__ out) {
    int t = blockIdx.x, i = threadIdx.x;
    float4 a = *(const float4*)(out + (size_t)t*HD + 4*i);
    float4 y0 = *(const float4*)(g_ybuf + (size_t)(2*t)*HD + 4*i);
    float4 y1 = *(const float4*)(g_ybuf + (size_t)(2*t+1)*HD + 4*i);
    a.x += y0.x + y1.x; a.y += y0.y + y1.y; a.z += y0.z + y1.z; a.w += y0.w + y1.w;
    *(float4*)(out + (size_t)t*HD + 4*i) = a;
}

// ---------------- launch ---------------------------------------------------
extern "C" void kernel_launch(void* const* d_in, const int* in_sizes, int n_in,
                              void* d_out, int out_size) {
    const float* x    = (const float*)d_in[0];
    const float* ln1  = (const float*)d_in[2];
    const float* ln2  = (const float*)d_in[3];
    const float* Wq   = (const float*)d_in[4];
    const float* Wkv  = (const float*)d_in[5];
    const float* Wo   = (const float*)d_in[6];
    const float* gate = (const float*)d_in[7];
    const float* w1   = (const float*)d_in[8];
    const float* w2   = (const float*)d_in[9];
    const float* sgu  = (const float*)d_in[10];
    const float* sdwn = (const float*)d_in[11];
    float* out = (float*)d_out;

    bf16 *p_wq_hi,*p_wq_lo,*p_wkv_hi,*p_wkv_lo,*p_wo_hi,*p_wo_lo;
    bf16 *p_h_hi,*p_h_lo,*p_o_hi,*p_o_lo;
    __half *p_w1h,*p_w2h,*p_sguh,*p_sdwnh,*p_h2h,*p_acth,*p_heh;
    float *p_q,*p_kv,*p_x2,*p_h2,*p_gu;
    cudaGetSymbolAddress((void**)&p_wq_hi,  g_wq_hi);
    cudaGetSymbolAddress((void**)&p_wq_lo,  g_wq_lo);
    cudaGetSymbolAddress((void**)&p_wkv_hi, g_wkv_hi);
    cudaGetSymbolAddress((void**)&p_wkv_lo, g_wkv_lo);
    cudaGetSymbolAddress((void**)&p_wo_hi,  g_wo_hi);
    cudaGetSymbolAddress((void**)&p_wo_lo,  g_wo_lo);
    cudaGetSymbolAddress((void**)&p_h_hi,   g_h_hi);
    cudaGetSymbolAddress((void**)&p_h_lo,   g_h_lo);
    cudaGetSymbolAddress((void**)&p_o_hi,   g_o_hi);
    cudaGetSymbolAddress((void**)&p_o_lo,   g_o_lo);
    cudaGetSymbolAddress((void**)&p_w1h,    g_w1h);
    cudaGetSymbolAddress((void**)&p_w2h,    g_w2h);
    cudaGetSymbolAddress((void**)&p_sguh,   g_sguh);
    cudaGetSymbolAddress((void**)&p_sdwnh,  g_sdwnh);
    cudaGetSymbolAddress((void**)&p_h2h,    g_h2h);
    cudaGetSymbolAddress((void**)&p_acth,   g_acth);
    cudaGetSymbolAddress((void**)&p_heh,    g_heh);
    cudaGetSymbolAddress((void**)&p_q,      g_q);
    cudaGetSymbolAddress((void**)&p_kv,     g_kv);
    cudaGetSymbolAddress((void**)&p_x2,     g_x2);
    cudaGetSymbolAddress((void**)&p_h2,     g_h2);
    cudaGetSymbolAddress((void**)&p_gu,     g_gu);

    cudaFuncSetAttribute(attn_tc_kernel, cudaFuncAttributeMaxDynamicSharedMemorySize, ATTN3_BYTES);
    const int SM_BF = 2 * STAGEB;     // 81920 B (2-stage bf16 3-pass)
    const int SM_HF = 3 * HSTAGE;     // 61440 B (3-stage fp16 1-pass)
    cudaFuncSetAttribute(gemm_bf3<0>, cudaFuncAttributeMaxDynamicSharedMemorySize, SM_BF);
    cudaFuncSetAttribute(gemm_bf3<1>, cudaFuncAttributeMaxDynamicSharedMemorySize, SM_BF);
    cudaFuncSetAttribute(gemm_hf<0>, cudaFuncAttributeMaxDynamicSharedMemorySize, SM_HF);
    cudaFuncSetAttribute(gemm_hf<1>, cudaFuncAttributeMaxDynamicSharedMemorySize, SM_HF);
    cudaFuncSetAttribute(gemm_hf<2>, cudaFuncAttributeMaxDynamicSharedMemorySize, SM_HF);
    cudaFuncSetAttribute(gemm_hf<3>, cudaFuncAttributeMaxDynamicSharedMemorySize, SM_HF);

    // weight preprocessing
    pack_wq_kernel<<<1024, 256>>>(Wq, p_wq_hi, p_wq_lo);
    split_kernel<<<2048, 256>>>(Wkv, p_wkv_hi, p_wkv_lo);
    split_kernel<<<1024, 256>>>(Wo, p_wo_hi, p_wo_lo);
    cvt_h_kernel<<<8192, 256>>>(w1, p_w1h);
    cvt_h_kernel<<<8192, 256>>>(w2, p_w2h);
    cvt_h_kernel<<<2048, 256>>>(sgu, p_sguh);
    cvt_h_kernel<<<1024, 256>>>(sdwn, p_sdwnh);

    // attention block (bf16 3-pass, routing-safe)
    rmsnorm_kernel<1><<<TT, 256>>>(x, ln1, p_h_hi, p_h_lo);
    gemm_bf3<0><<<dim3(8, 16), 256, SM_BF>>>(p_h_hi, p_h_lo, p_wq_hi, p_wq_lo,
                                             p_q, nullptr, 1024, 1024, 1024, 1024);
    gemm_bf3<0><<<dim3(16,16), 256, SM_BF>>>(p_h_hi, p_h_lo, p_wkv_hi, p_wkv_lo,
                                             p_kv, nullptr, 1024, 1024, 1024, 2048);
    attn_tc_kernel<<<dim3(16, NH, 2), 256, ATTN3_BYTES>>>(p_q, p_kv, p_o_hi, p_o_lo);
    gemm_bf3<1><<<dim3(8, 16), 256, SM_BF>>>(p_o_hi, p_o_lo, p_wo_hi, p_wo_lo,
                                             p_x2, x, 1024, 1024, 1024, 1024);

    // MoE block (gate on fp32 h2; GEMMs fp16 1-pass)
    rmsnorm_kernel<0><<<TT, 256>>>(p_x2, ln2, p_h2, nullptr);
    gate_kernel<<<TT, 256>>>(p_h2, gate);
    route_group_kernel<<<1, 256>>>();
    cvt_h_kernel<<<2048, 256>>>(p_h2, p_h2h);
    gemm_hf<2><<<dim3(8, 32, NEXP), 256, SM_HF>>>(p_h2h, p_w1h, nullptr, nullptr,
                                                  1024, 1024, 1024, 1024);
    gemm_hf<3><<<dim3(8, 32, NEXP), 256, SM_HF>>>(p_heh, p_w2h, nullptr, nullptr,
                                                  1024, 1024, 1024, 1024);

    // shared expert
    gemm_hf<0><<<dim3(16,16), 256, SM_HF>>>(p_h2h, p_sguh, p_gu, nullptr,
                                            1024, 1024, 1024, 2048);
    swiglu_kernel<<<TT, 256>>>(p_gu, p_acth);
    gemm_hf<1><<<dim3(8, 16), 256, SM_HF>>>(p_acth, p_sdwnh, out, p_x2,
                                            1024, 1024, 1024, 1024);

    // combine routed experts
    add_routed_kernel<<<TT, 256>>>(out);
}